// round 7
// baseline (speedup 1.0000x reference)
#include <cuda_runtime.h>
#include <cstdint>
#include <math.h>

#define BATCH 256
#define SEQ   512
#define HID   256
#define GATE3 768

#define USTRIDE 260   // padded k-stride (floats) for transposed weights
// smem: 3 * [64][260] weights + hT[8][256] + rhT[8][256] + z[8][64]
#define REC_SMEM_FLOATS (3*64*USTRIDE + 2048 + 2048 + 512)
#define REC_SMEM_BYTES  (REC_SMEM_FLOATS * 4)   // 218112 B

// Scratch (device global: sanctioned allocation-free scratch)
__device__ float g_A[SEQ * BATCH * GATE3];  // x@W_x + bias, [t][b][gate*256+j]

// ---------------------------------------------------------------------------
// helpers
// ---------------------------------------------------------------------------
__device__ __forceinline__ uint32_t smem_u32(const void* p) {
    uint32_t a;
    asm("{ .reg .u64 t; cvta.to.shared.u64 t, %1; cvt.u32.u64 %0, t; }"
        : "=r"(a) : "l"(p));
    return a;
}
__device__ __forceinline__ uint32_t mapa_peer(uint32_t addr, uint32_t rank) {
    uint32_t r;
    asm("mapa.shared::cluster.u32 %0, %1, %2;" : "=r"(r) : "r"(addr), "r"(rank));
    return r;
}
__device__ __forceinline__ void st_cluster_f32(uint32_t addr, float v) {
    asm volatile("st.shared::cluster.f32 [%0], %1;"
                 :: "r"(addr), "f"(v) : "memory");
}
__device__ __forceinline__ void cluster_sync_() {
    asm volatile("barrier.cluster.arrive.aligned;" ::: "memory");
    asm volatile("barrier.cluster.wait.aligned;" ::: "memory");
}
__device__ __forceinline__ float sigmoidf_(float v) { return 1.0f / (1.0f + expf(-v)); }

// ---- packed f32x2 (Blackwell FFMA2 path) ----
__device__ __forceinline__ unsigned long long packf2(float lo, float hi) {
    unsigned long long r;
    asm("mov.b64 %0, {%1, %2};" : "=l"(r)
        : "r"(__float_as_uint(lo)), "r"(__float_as_uint(hi)));
    return r;
}
__device__ __forceinline__ unsigned long long dupf2(float v) {
    unsigned long long r;
    uint32_t u = __float_as_uint(v);
    asm("mov.b64 %0, {%1, %1};" : "=l"(r) : "r"(u));
    return r;
}
__device__ __forceinline__ void ffma2(unsigned long long& d,
                                      unsigned long long a,
                                      unsigned long long b) {
    asm("fma.rn.f32x2 %0, %1, %2, %0;" : "+l"(d) : "l"(a), "l"(b));
}
__device__ __forceinline__ float2 unpackf2(unsigned long long v) {
    uint32_t lo, hi;
    asm("mov.b64 {%0, %1}, %2;" : "=r"(lo), "=r"(hi) : "l"(v));
    float2 f;
    f.x = __uint_as_float(lo);
    f.y = __uint_as_float(hi);
    return f;
}
__device__ __forceinline__ float hsumf2(unsigned long long a, unsigned long long b) {
    float2 p = unpackf2(a);
    float2 q = unpackf2(b);
    return (p.x + p.y) + (q.x + q.y);
}

// ---------------------------------------------------------------------------
// Precompute GEMM (FFMA2): g_A[t*256+b][g*256+j] = x[b,t,:] @ Wg[0:256,:] + bg
// ---------------------------------------------------------------------------
__global__ void __launch_bounds__(256)
precompute_kernel(const float* __restrict__ x,
                  const float* __restrict__ Wr, const float* __restrict__ br,
                  const float* __restrict__ Wz, const float* __restrict__ bz,
                  const float* __restrict__ Wh, const float* __restrict__ bh) {
    __shared__ float As[16][128];
    __shared__ float Bs[16][128];

    const int by = blockIdx.y;
    const float* W;  const float* bias;
    if (by < 2)      { W = Wr; bias = br; }
    else if (by < 4) { W = Wz; bias = bz; }
    else             { W = Wh; bias = bh; }
    const int cb = (by & 1) * 128;
    const int rowBase = blockIdx.x * 128;

    const int tid = threadIdx.x;
    const int tx = tid & 15;
    const int ty = tid >> 4;

    unsigned long long acc2[8][4];
#pragma unroll
    for (int i = 0; i < 8; i++)
#pragma unroll
        for (int j = 0; j < 4; j++) acc2[i][j] = 0ull;

    for (int k0 = 0; k0 < 256; k0 += 16) {
#pragma unroll
        for (int it = 0; it < 2; it++) {
            int idx = tid * 2 + it;
            int m   = idx >> 2;
            int k4  = (idx & 3) * 4;
            int row = rowBase + m;
            int b   = row & 255;
            int t   = row >> 8;
            float4 v = *reinterpret_cast<const float4*>(
                &x[(size_t)b * (SEQ * 256) + t * 256 + k0 + k4]);
            As[k4 + 0][m] = v.x;
            As[k4 + 1][m] = v.y;
            As[k4 + 2][m] = v.z;
            As[k4 + 3][m] = v.w;
        }
#pragma unroll
        for (int it = 0; it < 2; it++) {
            int idx = tid * 2 + it;
            int kk  = idx >> 5;
            int n4  = (idx & 31) * 4;
            *reinterpret_cast<float4*>(&Bs[kk][n4]) =
                *reinterpret_cast<const float4*>(&W[(k0 + kk) * 256 + cb + n4]);
        }
        __syncthreads();

#pragma unroll
        for (int kk = 0; kk < 16; kk++) {
            float4 a0 = *reinterpret_cast<const float4*>(&As[kk][ty * 4]);
            float4 a1 = *reinterpret_cast<const float4*>(&As[kk][64 + ty * 4]);
            float4 b0 = *reinterpret_cast<const float4*>(&Bs[kk][tx * 4]);
            float4 b1 = *reinterpret_cast<const float4*>(&Bs[kk][64 + tx * 4]);
            unsigned long long bp0 = packf2(b0.x, b0.y);
            unsigned long long bp1 = packf2(b0.z, b0.w);
            unsigned long long bp2 = packf2(b1.x, b1.y);
            unsigned long long bp3 = packf2(b1.z, b1.w);
            float av[8] = {a0.x, a0.y, a0.z, a0.w, a1.x, a1.y, a1.z, a1.w};
#pragma unroll
            for (int i = 0; i < 8; i++) {
                unsigned long long ad = dupf2(av[i]);
                ffma2(acc2[i][0], ad, bp0);
                ffma2(acc2[i][1], ad, bp1);
                ffma2(acc2[i][2], ad, bp2);
                ffma2(acc2[i][3], ad, bp3);
            }
        }
        __syncthreads();
    }

#pragma unroll
    for (int i = 0; i < 8; i++) {
        int m   = (i < 4) ? (ty * 4 + i) : (64 + ty * 4 + (i - 4));
        int row = rowBase + m;
        size_t base = (size_t)row * GATE3 + by * 128;
#pragma unroll
        for (int half = 0; half < 2; half++) {
            int ncol = half * 64 + tx * 4;
            float2 p0 = unpackf2(acc2[i][half * 2 + 0]);
            float2 p1 = unpackf2(acc2[i][half * 2 + 1]);
            float4 v;
            v.x = p0.x + bias[cb + ncol + 0];
            v.y = p0.y + bias[cb + ncol + 1];
            v.z = p1.x + bias[cb + ncol + 2];
            v.w = p1.y + bias[cb + ncol + 3];
            *reinterpret_cast<float4*>(&g_A[base + ncol]) = v;
        }
    }
}

// ---------------------------------------------------------------------------
// Recurrence: 32 clusters x 4 CTAs, CTA rank q owns hidden cols [q*64, q*64+64),
// cluster = 8 batch rows. All weights smem-resident, TRANSPOSED [col][k] so the
// k-contraction vectorizes: LDS.128 = 4 k-values = 2 f32x2 operands; state
// kept as hT[row][k] / rhT[row][k] (broadcast loads).
// ---------------------------------------------------------------------------
__global__ void __launch_bounds__(256, 1)
gru_recurrence_kernel(const float* __restrict__ Wr,
                      const float* __restrict__ Wz,
                      const float* __restrict__ Wh,
                      const float* __restrict__ Wo,
                      const float* __restrict__ bo,
                      float* __restrict__ out) {
    extern __shared__ char smem_raw[];
    float* UrT = (float*)smem_raw;           // [64][USTRIDE]
    float* UzT = UrT + 64 * USTRIDE;
    float* UhT = UzT + 64 * USTRIDE;
    float* hT  = UhT + 64 * USTRIDE;         // [8][256]
    float* rhT = hT + 2048;                  // [8][256]
    float* z_s = rhT + 2048;                 // [8][64]

    const int tid = threadIdx.x;
    const int q   = blockIdx.x & 3;
    const int b0  = (blockIdx.x >> 2) * 8;

    // phase-1 mapping: (g, col jj, row-half rp)
    const int g   = tid >> 7;
    const int jj  = (tid >> 1) & 63;
    const int rp  = tid & 1;
    const int jg  = q * 64 + jj;
    const int m0  = rp * 4;
    // phase-2 mapping: (col j2, row-pair rg)
    const int j2  = tid >> 2;
    const int rg  = tid & 3;
    const int jg2 = q * 64 + j2;
    const int r0  = rg * 2;

    // ---- preload transposed weight quarters: UgT[col][k] = Wg[(256+k)*256 + q*64+col]
    {
        int c  = tid & 63;
        int g4 = tid >> 6;   // 0..3 -> Ur, Uz, Uh, (dup of Uh rows split)
        for (int k = 0; k < 256; k++) {
            float v;
            if (g4 == 0)      v = Wr[(256 + k) * 256 + q * 64 + c];
            else if (g4 == 1) v = Wz[(256 + k) * 256 + q * 64 + c];
            else if (g4 == 2) v = Wh[(256 + k) * 256 + q * 64 + c];
            else              v = 0.f;
            if (g4 == 0)      UrT[c * USTRIDE + k] = v;
            else if (g4 == 1) UzT[c * USTRIDE + k] = v;
            else if (g4 == 2) UhT[c * USTRIDE + k] = v;
        }
    }
    for (int i = tid; i < 2048; i += 256) hT[i] = 0.f;
    __syncthreads();

    const float* __restrict__ Ucol  = (g ? UzT : UrT) + jj * USTRIDE;
    const float* __restrict__ Uhcol = UhT + j2 * USTRIDE;

    // remote peer base addresses (row-0 element of my column); row stride 1024B
    const uint32_t rh_loc = smem_u32(&rhT[jg]);
    const uint32_t h_loc  = smem_u32(&hT[jg2]);
    uint32_t rh_p[3], h_p[3];
#pragma unroll
    for (int i = 0; i < 3; i++) {
        rh_p[i] = mapa_peer(rh_loc, q ^ (i + 1));
        h_p[i]  = mapa_peer(h_loc,  q ^ (i + 1));
    }

    cluster_sync_();

    for (int t = 0; t < SEQ; t++) {
        const float* __restrict__ Arow = g_A + ((size_t)t * 256 + b0) * GATE3;

        // prefetch precomputed activations
        float a_g[4];
#pragma unroll
        for (int m = 0; m < 4; m++)
            a_g[m] = Arow[(m0 + m) * GATE3 + g * 256 + jg];
        float a_h0 = Arow[(r0 + 0) * GATE3 + 512 + jg2];
        float a_h1 = Arow[(r0 + 1) * GATE3 + 512 + jg2];

        // ---- phase 1: gate pre-activation h @ U_g (col jg, rows m0..m0+3) ----
        unsigned long long acc2[4][2];
#pragma unroll
        for (int i = 0; i < 4; i++) { acc2[i][0] = 0ull; acc2[i][1] = 0ull; }

#pragma unroll 8
        for (int k0 = 0; k0 < 256; k0 += 4) {
            ulonglong2 uv = *reinterpret_cast<const ulonglong2*>(&Ucol[k0]);
#pragma unroll
            for (int i = 0; i < 4; i++) {
                ulonglong2 hv = *reinterpret_cast<const ulonglong2*>(
                    &hT[(m0 + i) * 256 + k0]);
                ffma2(acc2[i][0], hv.x, uv.x);
                ffma2(acc2[i][1], hv.y, uv.y);
            }
        }

        if (g == 0) {
            float4 rh;
            float h_my[4];
#pragma unroll
            for (int i = 0; i < 4; i++) h_my[i] = hT[(m0 + i) * 256 + jg];
            rh.x = sigmoidf_(a_g[0] + hsumf2(acc2[0][0], acc2[0][1])) * h_my[0];
            rh.y = sigmoidf_(a_g[1] + hsumf2(acc2[1][0], acc2[1][1])) * h_my[1];
            rh.z = sigmoidf_(a_g[2] + hsumf2(acc2[2][0], acc2[2][1])) * h_my[2];
            rh.w = sigmoidf_(a_g[3] + hsumf2(acc2[3][0], acc2[3][1])) * h_my[3];
            float rv[4] = {rh.x, rh.y, rh.z, rh.w};
#pragma unroll
            for (int i = 0; i < 4; i++) {
                rhT[(m0 + i) * 256 + jg] = rv[i];
                uint32_t off = (m0 + i) * 1024;
                st_cluster_f32(rh_p[0] + off, rv[i]);
                st_cluster_f32(rh_p[1] + off, rv[i]);
                st_cluster_f32(rh_p[2] + off, rv[i]);
            }
        } else {
#pragma unroll
            for (int i = 0; i < 4; i++)
                z_s[(m0 + i) * 64 + jj] =
                    sigmoidf_(a_g[i] + hsumf2(acc2[i][0], acc2[i][1]));
        }

        cluster_sync_();   // (A) full rh visible cluster-wide; z local

        // ---- phase 2: h_cand = tanh(a_h + (r*h) @ Uh), rows r0, r0+1 ----
        unsigned long long ph0 = 0ull, ph1 = 0ull, ph2 = 0ull, ph3 = 0ull;
#pragma unroll 8
        for (int k0 = 0; k0 < 256; k0 += 4) {
            ulonglong2 uv  = *reinterpret_cast<const ulonglong2*>(&Uhcol[k0]);
            ulonglong2 ra  = *reinterpret_cast<const ulonglong2*>(
                &rhT[(r0 + 0) * 256 + k0]);
            ulonglong2 rb  = *reinterpret_cast<const ulonglong2*>(
                &rhT[(r0 + 1) * 256 + k0]);
            ffma2(ph0, ra.x, uv.x);
            ffma2(ph1, ra.y, uv.y);
            ffma2(ph2, rb.x, uv.x);
            ffma2(ph3, rb.y, uv.y);
        }
        float ah0 = hsumf2(ph0, ph1);
        float ah1 = hsumf2(ph2, ph3);

        float z0 = z_s[(r0 + 0) * 64 + j2];
        float z1 = z_s[(r0 + 1) * 64 + j2];
        float ho0 = hT[(r0 + 0) * 256 + jg2];
        float ho1 = hT[(r0 + 1) * 256 + jg2];
        float hc0 = tanhf(a_h0 + ah0);
        float hc1 = tanhf(a_h1 + ah1);
        float hn0 = z0 * ho0 + (1.f - z0) * hc0;
        float hn1 = z1 * ho1 + (1.f - z1) * hc1;

        hT[(r0 + 0) * 256 + jg2] = hn0;
        hT[(r0 + 1) * 256 + jg2] = hn1;
        {
            uint32_t off0 = (r0 + 0) * 1024;
            uint32_t off1 = (r0 + 1) * 1024;
#pragma unroll
            for (int i = 0; i < 3; i++) {
                st_cluster_f32(h_p[i] + off0, hn0);
                st_cluster_f32(h_p[i] + off1, hn1);
            }
        }

        cluster_sync_();   // (B) full updated h visible before next step
    }

    // ---- fused output: out[b0+r0+{0,1}, jg2] = h_last @ Wo[:, jg2] + bo ----
    float o0 = 0.f, o1 = 0.f;
#pragma unroll 8
    for (int k = 0; k < 256; k++) {
        float w  = Wo[k * 256 + jg2];
        float h0 = hT[(r0 + 0) * 256 + k];
        float h1 = hT[(r0 + 1) * 256 + k];
        o0 += h0 * w;
        o1 += h1 * w;
    }
    float bj = bo[jg2];
    out[(b0 + r0 + 0) * 256 + jg2] = o0 + bj;
    out[(b0 + r0 + 1) * 256 + jg2] = o1 + bj;
}

// ---------------------------------------------------------------------------
// Launch
// ---------------------------------------------------------------------------
extern "C" void kernel_launch(void* const* d_in, const int* in_sizes, int n_in,
                              void* d_out, int out_size) {
    const float* x  = (const float*)d_in[0];
    const float* Wr = (const float*)d_in[1];
    const float* br = (const float*)d_in[2];
    const float* Wz = (const float*)d_in[3];
    const float* bz = (const float*)d_in[4];
    const float* Wh = (const float*)d_in[5];
    const float* bh = (const float*)d_in[6];
    const float* Wo = (const float*)d_in[7];
    const float* bo = (const float*)d_in[8];
    float* out = (float*)d_out;

    precompute_kernel<<<dim3(1024, 6), 256>>>(x, Wr, br, Wz, bz, Wh, bh);

    cudaFuncSetAttribute(gru_recurrence_kernel,
                         cudaFuncAttributeMaxDynamicSharedMemorySize, REC_SMEM_BYTES);

    cudaLaunchConfig_t cfg = {};
    cfg.gridDim  = dim3(128, 1, 1);
    cfg.blockDim = dim3(256, 1, 1);
    cfg.dynamicSmemBytes = REC_SMEM_BYTES;
    cfg.stream = 0;
    cudaLaunchAttribute attrs[1];
    attrs[0].id = cudaLaunchAttributeClusterDimension;
    attrs[0].val.clusterDim.x = 4;
    attrs[0].val.clusterDim.y = 1;
    attrs[0].val.clusterDim.z = 1;
    cfg.attrs = attrs;
    cfg.numAttrs = 1;
    cudaLaunchKernelEx(&cfg, gru_recurrence_kernel, Wr, Wz, Wh, Wo, bo, out);
}

// round 8
// speedup vs baseline: 1.4228x; 1.4228x over previous
#include <cuda_runtime.h>
#include <cstdint>
#include <math.h>

#define BATCH 256
#define SEQ   512
#define HID   256
#define GATE3 768

// smem: Urz float2[256][64] (128K) + Uh float[256][64] (64K)
//     + hd float2[256][8] (16K) + rhd float2[256][8] (16K) + z_s float[8][64] (2K)
#define REC_SMEM_BYTES (131072 + 65536 + 16384 + 16384 + 2048)   // 231424

// Scratch (device global: sanctioned allocation-free scratch)
__device__ float g_A[SEQ * BATCH * GATE3];  // x@W_x + bias, [t][b][gate*256+j]

// ---------------------------------------------------------------------------
// helpers
// ---------------------------------------------------------------------------
__device__ __forceinline__ uint32_t smem_u32(const void* p) {
    uint32_t a;
    asm("{ .reg .u64 t; cvta.to.shared.u64 t, %1; cvt.u32.u64 %0, t; }"
        : "=r"(a) : "l"(p));
    return a;
}
__device__ __forceinline__ uint32_t mapa_peer(uint32_t addr, uint32_t rank) {
    uint32_t r;
    asm("mapa.shared::cluster.u32 %0, %1, %2;" : "=r"(r) : "r"(addr), "r"(rank));
    return r;
}
__device__ __forceinline__ void st_cluster_v4(uint32_t addr, float4 v) {
    asm volatile("st.shared::cluster.v4.f32 [%0], {%1,%2,%3,%4};"
                 :: "r"(addr), "f"(v.x), "f"(v.y), "f"(v.z), "f"(v.w) : "memory");
}
__device__ __forceinline__ void st_cluster_v2(uint32_t addr, float2 v) {
    asm volatile("st.shared::cluster.v2.f32 [%0], {%1,%2};"
                 :: "r"(addr), "f"(v.x), "f"(v.y) : "memory");
}
__device__ __forceinline__ void cluster_sync_() {
    asm volatile("barrier.cluster.arrive.aligned;" ::: "memory");
    asm volatile("barrier.cluster.wait.aligned;" ::: "memory");
}
__device__ __forceinline__ float sigmoidf_(float v) { return 1.0f / (1.0f + expf(-v)); }

// ---- packed f32x2 (Blackwell FFMA2 path) ----
__device__ __forceinline__ unsigned long long packf2(float lo, float hi) {
    unsigned long long r;
    asm("mov.b64 %0, {%1, %2};" : "=l"(r)
        : "r"(__float_as_uint(lo)), "r"(__float_as_uint(hi)));
    return r;
}
__device__ __forceinline__ unsigned long long dupf2(float v) {
    unsigned long long r;
    uint32_t u = __float_as_uint(v);
    asm("mov.b64 %0, {%1, %1};" : "=l"(r) : "r"(u));
    return r;
}
__device__ __forceinline__ void ffma2(unsigned long long& d,
                                      unsigned long long a,
                                      unsigned long long b) {
    asm("fma.rn.f32x2 %0, %1, %2, %0;" : "+l"(d) : "l"(a), "l"(b));
}
__device__ __forceinline__ float2 unpackf2(unsigned long long v) {
    uint32_t lo, hi;
    asm("mov.b64 {%0, %1}, %2;" : "=r"(lo), "=r"(hi) : "l"(v));
    float2 f;
    f.x = __uint_as_float(lo);
    f.y = __uint_as_float(hi);
    return f;
}

// ---------------------------------------------------------------------------
// Precompute GEMM (FFMA2): g_A[t*256+b][g*256+j] = x[b,t,:] @ Wg[0:256,:] + bg
// ---------------------------------------------------------------------------
__global__ void __launch_bounds__(256)
precompute_kernel(const float* __restrict__ x,
                  const float* __restrict__ Wr, const float* __restrict__ br,
                  const float* __restrict__ Wz, const float* __restrict__ bz,
                  const float* __restrict__ Wh, const float* __restrict__ bh) {
    __shared__ float As[16][128];
    __shared__ float Bs[16][128];

    const int by = blockIdx.y;
    const float* W;  const float* bias;
    if (by < 2)      { W = Wr; bias = br; }
    else if (by < 4) { W = Wz; bias = bz; }
    else             { W = Wh; bias = bh; }
    const int cb = (by & 1) * 128;
    const int rowBase = blockIdx.x * 128;

    const int tid = threadIdx.x;
    const int tx = tid & 15;
    const int ty = tid >> 4;

    unsigned long long acc2[8][4];
#pragma unroll
    for (int i = 0; i < 8; i++)
#pragma unroll
        for (int j = 0; j < 4; j++) acc2[i][j] = 0ull;

    for (int k0 = 0; k0 < 256; k0 += 16) {
#pragma unroll
        for (int it = 0; it < 2; it++) {
            int idx = tid * 2 + it;
            int m   = idx >> 2;
            int k4  = (idx & 3) * 4;
            int row = rowBase + m;
            int b   = row & 255;
            int t   = row >> 8;
            float4 v = *reinterpret_cast<const float4*>(
                &x[(size_t)b * (SEQ * 256) + t * 256 + k0 + k4]);
            As[k4 + 0][m] = v.x;
            As[k4 + 1][m] = v.y;
            As[k4 + 2][m] = v.z;
            As[k4 + 3][m] = v.w;
        }
#pragma unroll
        for (int it = 0; it < 2; it++) {
            int idx = tid * 2 + it;
            int kk  = idx >> 5;
            int n4  = (idx & 31) * 4;
            *reinterpret_cast<float4*>(&Bs[kk][n4]) =
                *reinterpret_cast<const float4*>(&W[(k0 + kk) * 256 + cb + n4]);
        }
        __syncthreads();

#pragma unroll
        for (int kk = 0; kk < 16; kk++) {
            float4 a0 = *reinterpret_cast<const float4*>(&As[kk][ty * 4]);
            float4 a1 = *reinterpret_cast<const float4*>(&As[kk][64 + ty * 4]);
            float4 b0 = *reinterpret_cast<const float4*>(&Bs[kk][tx * 4]);
            float4 b1 = *reinterpret_cast<const float4*>(&Bs[kk][64 + tx * 4]);
            unsigned long long bp0 = packf2(b0.x, b0.y);
            unsigned long long bp1 = packf2(b0.z, b0.w);
            unsigned long long bp2 = packf2(b1.x, b1.y);
            unsigned long long bp3 = packf2(b1.z, b1.w);
            float av[8] = {a0.x, a0.y, a0.z, a0.w, a1.x, a1.y, a1.z, a1.w};
#pragma unroll
            for (int i = 0; i < 8; i++) {
                unsigned long long ad = dupf2(av[i]);
                ffma2(acc2[i][0], ad, bp0);
                ffma2(acc2[i][1], ad, bp1);
                ffma2(acc2[i][2], ad, bp2);
                ffma2(acc2[i][3], ad, bp3);
            }
        }
        __syncthreads();
    }

#pragma unroll
    for (int i = 0; i < 8; i++) {
        int m   = (i < 4) ? (ty * 4 + i) : (64 + ty * 4 + (i - 4));
        int row = rowBase + m;
        size_t base = (size_t)row * GATE3 + by * 128;
#pragma unroll
        for (int half = 0; half < 2; half++) {
            int ncol = half * 64 + tx * 4;
            float2 p0 = unpackf2(acc2[i][half * 2 + 0]);
            float2 p1 = unpackf2(acc2[i][half * 2 + 1]);
            float4 v;
            v.x = p0.x + bias[cb + ncol + 0];
            v.y = p0.y + bias[cb + ncol + 1];
            v.z = p1.x + bias[cb + ncol + 2];
            v.w = p1.y + bias[cb + ncol + 3];
            *reinterpret_cast<float4*>(&g_A[base + ncol]) = v;
        }
    }
}

// ---------------------------------------------------------------------------
// Recurrence: 32 clusters x 4 CTAs, CTA rank q owns hidden cols [q*64, q*64+64),
// cluster = 8 batch rows. Weights [k][col] (conflict-free); state DUPLICATED in
// smem as float2 {v,v} so f32x2 FMAs need no dup-movs:
//   phase1 per k: LDS.64 (ur,uz) + LDS.128 {h,h}{h',h'} + 2 FFMA2  (4 MACs)
//   phase2 per k: LDS.64 (uh,uh') + LDS.64 {rh,rh}      + 1 FFMA2  (2 MACs)
// Phase1 thread (jj, rq): col jj, both gates, rows 2rq,2rq+1.
// Phase2 thread (jp, r):  cols 2jp,2jp+1, row r.
// ---------------------------------------------------------------------------
__global__ void __launch_bounds__(256, 1)
gru_recurrence_kernel(const float* __restrict__ Wr,
                      const float* __restrict__ Wz,
                      const float* __restrict__ Wh,
                      const float* __restrict__ Wo,
                      const float* __restrict__ bo,
                      float* __restrict__ out) {
    extern __shared__ char smem_raw[];
    float2* Urz = (float2*)smem_raw;                       // [256][64] (k, col)
    float*  Uh  = (float*)(smem_raw + 131072);             // [256][64]
    float2* hd  = (float2*)(smem_raw + 131072 + 65536);    // [256 cols][8 rows] {h,h}
    float2* rhd = hd + 2048;                               // [256][8] {rh,rh}
    float*  z_s = (float*)(rhd + 2048);                    // [8 rows][64 cols]

    const int tid = threadIdx.x;
    const int q   = blockIdx.x & 3;
    const int b0  = (blockIdx.x >> 2) * 8;

    // phase-1 mapping
    const int jj  = tid >> 2;          // 0..63
    const int rq  = tid & 3;
    const int m0  = rq * 2;            // rows m0, m0+1
    const int jg  = q * 64 + jj;
    // phase-2 mapping
    const int jp  = tid >> 3;          // 0..31
    const int r   = tid & 7;
    const int c0  = jp * 2;            // local cols c0, c0+1
    const int gc0 = q * 64 + c0;

    // ---- preload weights: Urz[k][c] = (Wr,Wz)[(256+k)][q*64+c], Uh[k][c] ----
    for (int i = tid; i < 16384; i += 256) {
        int k = i >> 6, c = i & 63;
        int gi = (256 + k) * 256 + q * 64 + c;
        Urz[i] = make_float2(Wr[gi], Wz[gi]);
        Uh[i]  = Wh[gi];
    }
    for (int i = tid; i < 2048; i += 256) hd[i] = make_float2(0.f, 0.f);
    __syncthreads();

    // remote peer addresses
    const uint32_t rh_loc = smem_u32(&rhd[jg * 8 + m0]);        // 16B (2 rows)
    const uint32_t h0_loc = smem_u32(&hd[gc0 * 8 + r]);         // 8B
    const uint32_t h1_loc = smem_u32(&hd[(gc0 + 1) * 8 + r]);   // 8B
    uint32_t rh_p[3], h0_p[3], h1_p[3];
#pragma unroll
    for (int i = 0; i < 3; i++) {
        rh_p[i] = mapa_peer(rh_loc, q ^ (i + 1));
        h0_p[i] = mapa_peer(h0_loc, q ^ (i + 1));
        h1_p[i] = mapa_peer(h1_loc, q ^ (i + 1));
    }

    cluster_sync_();

    for (int t = 0; t < SEQ; t++) {
        const float* __restrict__ Arow = g_A + ((size_t)t * 256 + b0) * GATE3;

        // prefetch precomputed activations (DRAM)
        float a_r0 = Arow[(m0 + 0) * GATE3 + jg];
        float a_r1 = Arow[(m0 + 1) * GATE3 + jg];
        float a_z0 = Arow[(m0 + 0) * GATE3 + 256 + jg];
        float a_z1 = Arow[(m0 + 1) * GATE3 + 256 + jg];
        float2 ah2 = *reinterpret_cast<const float2*>(&Arow[r * GATE3 + 512 + gc0]);

        // ---- phase 1: (r,z) pre-activations for col jg, rows m0..m0+1 ----
        unsigned long long acc0 = 0ull, acc1 = 0ull;
#pragma unroll 8
        for (int k = 0; k < 256; k++) {
            unsigned long long u2 =
                *reinterpret_cast<const unsigned long long*>(&Urz[k * 64 + jj]);
            ulonglong2 hv = *reinterpret_cast<const ulonglong2*>(&hd[k * 8 + m0]);
            ffma2(acc0, hv.x, u2);
            ffma2(acc1, hv.y, u2);
        }
        float2 p0 = unpackf2(acc0);   // (r_pre, z_pre) row m0
        float2 p1 = unpackf2(acc1);   // row m0+1

        float hm0 = hd[jg * 8 + m0 + 0].x;
        float hm1 = hd[jg * 8 + m0 + 1].x;
        float rv0 = sigmoidf_(a_r0 + p0.x);
        float rv1 = sigmoidf_(a_r1 + p1.x);
        float zv0 = sigmoidf_(a_z0 + p0.y);
        float zv1 = sigmoidf_(a_z1 + p1.y);
        float rh0 = rv0 * hm0;
        float rh1 = rv1 * hm1;

        float4 rhv = make_float4(rh0, rh0, rh1, rh1);
        *reinterpret_cast<float4*>(&rhd[jg * 8 + m0]) = rhv;
        st_cluster_v4(rh_p[0], rhv);
        st_cluster_v4(rh_p[1], rhv);
        st_cluster_v4(rh_p[2], rhv);
        z_s[(m0 + 0) * 64 + jj] = zv0;
        z_s[(m0 + 1) * 64 + jj] = zv1;

        cluster_sync_();   // (A) full rh (duplicated) visible cluster-wide

        // ---- phase 2: h_cand for cols gc0,gc0+1, row r ----
        unsigned long long acc = 0ull;
#pragma unroll 8
        for (int k = 0; k < 256; k++) {
            unsigned long long u2 =
                *reinterpret_cast<const unsigned long long*>(&Uh[k * 64 + c0]);
            unsigned long long rv =
                *reinterpret_cast<const unsigned long long*>(&rhd[k * 8 + r]);
            ffma2(acc, rv, u2);
        }
        float2 pc = unpackf2(acc);

        float2 zz = *reinterpret_cast<const float2*>(&z_s[r * 64 + c0]);
        float ho0 = hd[gc0 * 8 + r].x;
        float ho1 = hd[(gc0 + 1) * 8 + r].x;
        float hc0 = tanhf(ah2.x + pc.x);
        float hc1 = tanhf(ah2.y + pc.y);
        float hn0 = zz.x * ho0 + (1.f - zz.x) * hc0;
        float hn1 = zz.y * ho1 + (1.f - zz.y) * hc1;

        float2 d0 = make_float2(hn0, hn0);
        float2 d1 = make_float2(hn1, hn1);
        hd[gc0 * 8 + r]       = d0;
        hd[(gc0 + 1) * 8 + r] = d1;
#pragma unroll
        for (int i = 0; i < 3; i++) {
            st_cluster_v2(h0_p[i], d0);
            st_cluster_v2(h1_p[i], d1);
        }

        cluster_sync_();   // (B) full updated h visible before next step
    }

    // ---- fused output: out[b0+r, gc0..gc0+1] = h_last @ Wo + bo ----
    unsigned long long o2 = 0ull;
#pragma unroll 8
    for (int k = 0; k < 256; k++) {
        unsigned long long w2 =
            *reinterpret_cast<const unsigned long long*>(&Wo[k * 256 + gc0]);
        unsigned long long hv =
            *reinterpret_cast<const unsigned long long*>(&hd[k * 8 + r]);
        ffma2(o2, hv, w2);
    }
    float2 oo = unpackf2(o2);
    float2 bb = *reinterpret_cast<const float2*>(&bo[gc0]);
    out[(b0 + r) * 256 + gc0 + 0] = oo.x + bb.x;
    out[(b0 + r) * 256 + gc0 + 1] = oo.y + bb.y;
}

// ---------------------------------------------------------------------------
// Launch
// ---------------------------------------------------------------------------
extern "C" void kernel_launch(void* const* d_in, const int* in_sizes, int n_in,
                              void* d_out, int out_size) {
    const float* x  = (const float*)d_in[0];
    const float* Wr = (const float*)d_in[1];
    const float* br = (const float*)d_in[2];
    const float* Wz = (const float*)d_in[3];
    const float* bz = (const float*)d_in[4];
    const float* Wh = (const float*)d_in[5];
    const float* bh = (const float*)d_in[6];
    const float* Wo = (const float*)d_in[7];
    const float* bo = (const float*)d_in[8];
    float* out = (float*)d_out;

    precompute_kernel<<<dim3(1024, 6), 256>>>(x, Wr, br, Wz, bz, Wh, bh);

    cudaFuncSetAttribute(gru_recurrence_kernel,
                         cudaFuncAttributeMaxDynamicSharedMemorySize, REC_SMEM_BYTES);

    cudaLaunchConfig_t cfg = {};
    cfg.gridDim  = dim3(128, 1, 1);
    cfg.blockDim = dim3(256, 1, 1);
    cfg.dynamicSmemBytes = REC_SMEM_BYTES;
    cfg.stream = 0;
    cudaLaunchAttribute attrs[1];
    attrs[0].id = cudaLaunchAttributeClusterDimension;
    attrs[0].val.clusterDim.x = 4;
    attrs[0].val.clusterDim.y = 1;
    attrs[0].val.clusterDim.z = 1;
    cfg.attrs = attrs;
    cfg.numAttrs = 1;
    cudaLaunchKernelEx(&cfg, gru_recurrence_kernel, Wr, Wz, Wh, Wo, bo, out);
}

// round 9
// speedup vs baseline: 1.9874x; 1.3968x over previous
#include <cuda_runtime.h>
#include <cstdint>
#include <math.h>

#define BATCH 256
#define SEQ   512
#define HID   256
#define GATE3 768

// smem floats: Ur 16384 + Uz 16384 + Uh 16384 + hT 2048 + rhT 2048 + z 512 + red 1536
#define REC_SMEM_FLOATS (16384*3 + 2048 + 2048 + 512 + 1536)
#define REC_SMEM_BYTES  (REC_SMEM_FLOATS * 4)   // 221184

// Scratch (device global: sanctioned allocation-free scratch)
__device__ float g_A[SEQ * BATCH * GATE3];  // x@W_x + bias, [t][b][gate*256+j]

// ---------------------------------------------------------------------------
// helpers
// ---------------------------------------------------------------------------
__device__ __forceinline__ uint32_t smem_u32(const void* p) {
    uint32_t a;
    asm("{ .reg .u64 t; cvta.to.shared.u64 t, %1; cvt.u32.u64 %0, t; }"
        : "=r"(a) : "l"(p));
    return a;
}
__device__ __forceinline__ uint32_t mapa_peer(uint32_t addr, uint32_t rank) {
    uint32_t r;
    asm("mapa.shared::cluster.u32 %0, %1, %2;" : "=r"(r) : "r"(addr), "r"(rank));
    return r;
}
__device__ __forceinline__ void st_cluster_v4(uint32_t addr, float4 v) {
    asm volatile("st.shared::cluster.v4.f32 [%0], {%1,%2,%3,%4};"
                 :: "r"(addr), "f"(v.x), "f"(v.y), "f"(v.z), "f"(v.w) : "memory");
}
__device__ __forceinline__ void cluster_sync_() {
    asm volatile("barrier.cluster.arrive.aligned;" ::: "memory");
    asm volatile("barrier.cluster.wait.aligned;" ::: "memory");
}
__device__ __forceinline__ float sigmoidf_(float v) { return 1.0f / (1.0f + expf(-v)); }

// ---- packed f32x2 (used only in the precompute GEMM) ----
__device__ __forceinline__ unsigned long long packf2(float lo, float hi) {
    unsigned long long r;
    asm("mov.b64 %0, {%1, %2};" : "=l"(r)
        : "r"(__float_as_uint(lo)), "r"(__float_as_uint(hi)));
    return r;
}
__device__ __forceinline__ unsigned long long dupf2(float v) {
    unsigned long long r;
    uint32_t u = __float_as_uint(v);
    asm("mov.b64 %0, {%1, %1};" : "=l"(r) : "r"(u));
    return r;
}
__device__ __forceinline__ void ffma2(unsigned long long& d,
                                      unsigned long long a,
                                      unsigned long long b) {
    asm("fma.rn.f32x2 %0, %1, %2, %0;" : "+l"(d) : "l"(a), "l"(b));
}
__device__ __forceinline__ float2 unpackf2(unsigned long long v) {
    uint32_t lo, hi;
    asm("mov.b64 {%0, %1}, %2;" : "=r"(lo), "=r"(hi) : "l"(v));
    float2 f;
    f.x = __uint_as_float(lo);
    f.y = __uint_as_float(hi);
    return f;
}

// ---------------------------------------------------------------------------
// Precompute GEMM (unchanged, passing): g_A = x @ W_x + bias
// ---------------------------------------------------------------------------
__global__ void __launch_bounds__(256)
precompute_kernel(const float* __restrict__ x,
                  const float* __restrict__ Wr, const float* __restrict__ br,
                  const float* __restrict__ Wz, const float* __restrict__ bz,
                  const float* __restrict__ Wh, const float* __restrict__ bh) {
    __shared__ float As[16][128];
    __shared__ float Bs[16][128];

    const int by = blockIdx.y;
    const float* W;  const float* bias;
    if (by < 2)      { W = Wr; bias = br; }
    else if (by < 4) { W = Wz; bias = bz; }
    else             { W = Wh; bias = bh; }
    const int cb = (by & 1) * 128;
    const int rowBase = blockIdx.x * 128;

    const int tid = threadIdx.x;
    const int tx = tid & 15;
    const int ty = tid >> 4;

    unsigned long long acc2[8][4];
#pragma unroll
    for (int i = 0; i < 8; i++)
#pragma unroll
        for (int j = 0; j < 4; j++) acc2[i][j] = 0ull;

    for (int k0 = 0; k0 < 256; k0 += 16) {
#pragma unroll
        for (int it = 0; it < 2; it++) {
            int idx = tid * 2 + it;
            int m   = idx >> 2;
            int k4  = (idx & 3) * 4;
            int row = rowBase + m;
            int b   = row & 255;
            int t   = row >> 8;
            float4 v = *reinterpret_cast<const float4*>(
                &x[(size_t)b * (SEQ * 256) + t * 256 + k0 + k4]);
            As[k4 + 0][m] = v.x;
            As[k4 + 1][m] = v.y;
            As[k4 + 2][m] = v.z;
            As[k4 + 3][m] = v.w;
        }
#pragma unroll
        for (int it = 0; it < 2; it++) {
            int idx = tid * 2 + it;
            int kk  = idx >> 5;
            int n4  = (idx & 31) * 4;
            *reinterpret_cast<float4*>(&Bs[kk][n4]) =
                *reinterpret_cast<const float4*>(&W[(k0 + kk) * 256 + cb + n4]);
        }
        __syncthreads();

#pragma unroll
        for (int kk = 0; kk < 16; kk++) {
            float4 a0 = *reinterpret_cast<const float4*>(&As[kk][ty * 4]);
            float4 a1 = *reinterpret_cast<const float4*>(&As[kk][64 + ty * 4]);
            float4 b0 = *reinterpret_cast<const float4*>(&Bs[kk][tx * 4]);
            float4 b1 = *reinterpret_cast<const float4*>(&Bs[kk][64 + tx * 4]);
            unsigned long long bp0 = packf2(b0.x, b0.y);
            unsigned long long bp1 = packf2(b0.z, b0.w);
            unsigned long long bp2 = packf2(b1.x, b1.y);
            unsigned long long bp3 = packf2(b1.z, b1.w);
            float av[8] = {a0.x, a0.y, a0.z, a0.w, a1.x, a1.y, a1.z, a1.w};
#pragma unroll
            for (int i = 0; i < 8; i++) {
                unsigned long long ad = dupf2(av[i]);
                ffma2(acc2[i][0], ad, bp0);
                ffma2(acc2[i][1], ad, bp1);
                ffma2(acc2[i][2], ad, bp2);
                ffma2(acc2[i][3], ad, bp3);
            }
        }
        __syncthreads();
    }

#pragma unroll
    for (int i = 0; i < 8; i++) {
        int m   = (i < 4) ? (ty * 4 + i) : (64 + ty * 4 + (i - 4));
        int row = rowBase + m;
        size_t base = (size_t)row * GATE3 + by * 128;
#pragma unroll
        for (int half = 0; half < 2; half++) {
            int ncol = half * 64 + tx * 4;
            float2 p0 = unpackf2(acc2[i][half * 2 + 0]);
            float2 p1 = unpackf2(acc2[i][half * 2 + 1]);
            float4 v;
            v.x = p0.x + bias[cb + ncol + 0];
            v.y = p0.y + bias[cb + ncol + 1];
            v.z = p1.x + bias[cb + ncol + 2];
            v.w = p1.y + bias[cb + ncol + 3];
            *reinterpret_cast<float4*>(&g_A[base + ncol]) = v;
        }
    }
}

// ---------------------------------------------------------------------------
// Recurrence: 32 clusters x 4 CTAs, CTA rank q owns cols [q*64, q*64+64),
// cluster = 8 batch rows, state [col][8 rows] in smem.
// Phase1: thread (jj, g, ks) — 8 rows per weight-load, k-split 2 + reduction.
//   per k: LDS.32 weight (full 128B wavefront) + 2x LDS.128 broadcast h + 8 FFMA.
// Phase2: thread (c, kq) — 8 rows, k-split 4 + reduction.
// ---------------------------------------------------------------------------
__global__ void __launch_bounds__(256, 1)
gru_recurrence_kernel(const float* __restrict__ Wr,
                      const float* __restrict__ Wz,
                      const float* __restrict__ Wh,
                      const float* __restrict__ Wo,
                      const float* __restrict__ bo,
                      float* __restrict__ out) {
    extern __shared__ float sm[];
    float* Ur_s = sm;                    // [256][64]
    float* Uz_s = Ur_s + 16384;
    float* Uh_s = Uz_s + 16384;
    float* hT   = Uh_s + 16384;          // [256 cols][8 rows]
    float* rhT  = hT + 2048;             // [256 cols][8 rows]
    float* z_s  = rhT + 2048;            // [64 cols][8 rows]
    float* red  = z_s + 512;             // [192][8] reduction scratch

    const int tid = threadIdx.x;
    const int q   = blockIdx.x & 3;
    const int b0  = (blockIdx.x >> 2) * 8;

    // phase-1 mapping
    const int jj = tid & 63;
    const int g  = (tid >> 6) & 1;
    const int ks = tid >> 7;             // k-half
    const int jg = q * 64 + jj;
    // phase-2 mapping
    const int c  = tid & 63;
    const int kq = tid >> 6;             // k-quarter
    const int gc = q * 64 + c;

    // ---- preload weight quarters ----
    for (int i = tid; i < 16384; i += 256) {
        int k = i >> 6, cc = i & 63;
        int gi = (256 + k) * 256 + q * 64 + cc;
        Ur_s[i] = Wr[gi];
        Uz_s[i] = Wz[gi];
        Uh_s[i] = Wh[gi];
    }
    for (int i = tid; i < 2048; i += 256) hT[i] = 0.f;
    __syncthreads();

    const float* __restrict__ Ug = g ? Uz_s : Ur_s;
    const int k1_0 = ks * 128;           // phase-1 k range start
    const int k2_0 = kq * 64;            // phase-2 k range start

    // peer addresses: rhT[jg][0..7] and hT[gc][0..7] (32B each = 2x 16B)
    const uint32_t rh_loc = smem_u32(&rhT[jg * 8]);
    const uint32_t h_loc  = smem_u32(&hT[gc * 8]);
    uint32_t rh_p[3], h_p[3];
#pragma unroll
    for (int i = 0; i < 3; i++) {
        rh_p[i] = mapa_peer(rh_loc, q ^ (i + 1));
        h_p[i]  = mapa_peer(h_loc,  q ^ (i + 1));
    }

    cluster_sync_();

    for (int t = 0; t < SEQ; t++) {
        const float* __restrict__ Arow = g_A + ((size_t)t * 256 + b0) * GATE3;

        // prefetch activations (DRAM), consumed post-reduction
        float a_g[8];
        if (ks == 0) {
#pragma unroll
            for (int m = 0; m < 8; m++)
                a_g[m] = Arow[m * GATE3 + g * 256 + jg];
        }
        float a_h[8];
        if (kq == 0) {
#pragma unroll
            for (int m = 0; m < 8; m++)
                a_h[m] = Arow[m * GATE3 + 512 + gc];
        }

        // ---- phase 1: gate pre-activation, col jj gate g, 8 rows, half-k ----
        float acc[8];
#pragma unroll
        for (int i = 0; i < 8; i++) acc[i] = 0.f;
#pragma unroll 4
        for (int kk = 0; kk < 128; kk++) {
            int k = k1_0 + kk;
            float  u  = Ug[k * 64 + jj];
            float4 hA = *reinterpret_cast<const float4*>(&hT[k * 8]);
            float4 hB = *reinterpret_cast<const float4*>(&hT[k * 8 + 4]);
            acc[0] += u * hA.x;  acc[1] += u * hA.y;
            acc[2] += u * hA.z;  acc[3] += u * hA.w;
            acc[4] += u * hB.x;  acc[5] += u * hB.y;
            acc[6] += u * hB.z;  acc[7] += u * hB.w;
        }

        if (ks == 1) {
            float* rd = &red[(tid - 128) * 8];
            *reinterpret_cast<float4*>(rd)     = make_float4(acc[0], acc[1], acc[2], acc[3]);
            *reinterpret_cast<float4*>(rd + 4) = make_float4(acc[4], acc[5], acc[6], acc[7]);
        }
        __syncthreads();
        if (ks == 0) {
            const float* rd = &red[tid * 8];
            float4 rA = *reinterpret_cast<const float4*>(rd);
            float4 rB = *reinterpret_cast<const float4*>(rd + 4);
            acc[0] += rA.x; acc[1] += rA.y; acc[2] += rA.z; acc[3] += rA.w;
            acc[4] += rB.x; acc[5] += rB.y; acc[6] += rB.z; acc[7] += rB.w;

            if (g == 0) {
                float4 h0 = *reinterpret_cast<const float4*>(&hT[jg * 8]);
                float4 h1 = *reinterpret_cast<const float4*>(&hT[jg * 8 + 4]);
                float hm[8] = {h0.x, h0.y, h0.z, h0.w, h1.x, h1.y, h1.z, h1.w};
                float rv[8];
#pragma unroll
                for (int m = 0; m < 8; m++)
                    rv[m] = sigmoidf_(a_g[m] + acc[m]) * hm[m];
                float4 vA = make_float4(rv[0], rv[1], rv[2], rv[3]);
                float4 vB = make_float4(rv[4], rv[5], rv[6], rv[7]);
                *reinterpret_cast<float4*>(&rhT[jg * 8])     = vA;
                *reinterpret_cast<float4*>(&rhT[jg * 8 + 4]) = vB;
#pragma unroll
                for (int i = 0; i < 3; i++) {
                    st_cluster_v4(rh_p[i], vA);
                    st_cluster_v4(rh_p[i] + 16, vB);
                }
            } else {
                float zv[8];
#pragma unroll
                for (int m = 0; m < 8; m++)
                    zv[m] = sigmoidf_(a_g[m] + acc[m]);
                *reinterpret_cast<float4*>(&z_s[jj * 8]) =
                    make_float4(zv[0], zv[1], zv[2], zv[3]);
                *reinterpret_cast<float4*>(&z_s[jj * 8 + 4]) =
                    make_float4(zv[4], zv[5], zv[6], zv[7]);
            }
        }

        cluster_sync_();   // (A) rh visible cluster-wide; z local

        // ---- phase 2: h_cand pre-act, col c, 8 rows, quarter-k ----
        float ach[8];
#pragma unroll
        for (int i = 0; i < 8; i++) ach[i] = 0.f;
#pragma unroll 4
        for (int kk = 0; kk < 64; kk++) {
            int k = k2_0 + kk;
            float  u  = Uh_s[k * 64 + c];
            float4 rA = *reinterpret_cast<const float4*>(&rhT[k * 8]);
            float4 rB = *reinterpret_cast<const float4*>(&rhT[k * 8 + 4]);
            ach[0] += u * rA.x;  ach[1] += u * rA.y;
            ach[2] += u * rA.z;  ach[3] += u * rA.w;
            ach[4] += u * rB.x;  ach[5] += u * rB.y;
            ach[6] += u * rB.z;  ach[7] += u * rB.w;
        }

        if (kq > 0) {
            float* rd = &red[((kq - 1) * 64 + c) * 8];
            *reinterpret_cast<float4*>(rd)     = make_float4(ach[0], ach[1], ach[2], ach[3]);
            *reinterpret_cast<float4*>(rd + 4) = make_float4(ach[4], ach[5], ach[6], ach[7]);
        }
        __syncthreads();
        if (kq == 0) {
#pragma unroll
            for (int p = 0; p < 3; p++) {
                const float* rd = &red[(p * 64 + c) * 8];
                float4 rA = *reinterpret_cast<const float4*>(rd);
                float4 rB = *reinterpret_cast<const float4*>(rd + 4);
                ach[0] += rA.x; ach[1] += rA.y; ach[2] += rA.z; ach[3] += rA.w;
                ach[4] += rB.x; ach[5] += rB.y; ach[6] += rB.z; ach[7] += rB.w;
            }

            float4 z0 = *reinterpret_cast<const float4*>(&z_s[c * 8]);
            float4 z1 = *reinterpret_cast<const float4*>(&z_s[c * 8 + 4]);
            float4 h0 = *reinterpret_cast<const float4*>(&hT[gc * 8]);
            float4 h1 = *reinterpret_cast<const float4*>(&hT[gc * 8 + 4]);
            float zz[8] = {z0.x, z0.y, z0.z, z0.w, z1.x, z1.y, z1.z, z1.w};
            float ho[8] = {h0.x, h0.y, h0.z, h0.w, h1.x, h1.y, h1.z, h1.w};
            float hn[8];
#pragma unroll
            for (int m = 0; m < 8; m++) {
                float hc = tanhf(a_h[m] + ach[m]);
                hn[m] = zz[m] * ho[m] + (1.f - zz[m]) * hc;
            }
            float4 vA = make_float4(hn[0], hn[1], hn[2], hn[3]);
            float4 vB = make_float4(hn[4], hn[5], hn[6], hn[7]);
            *reinterpret_cast<float4*>(&hT[gc * 8])     = vA;
            *reinterpret_cast<float4*>(&hT[gc * 8 + 4]) = vB;
#pragma unroll
            for (int i = 0; i < 3; i++) {
                st_cluster_v4(h_p[i], vA);
                st_cluster_v4(h_p[i] + 16, vB);
            }
        }

        cluster_sync_();   // (B) full updated h visible before next step
    }

    // ---- fused output: out[b0+m, gc] = h_last[m] @ Wo[:, gc] + bo[gc] ----
    if (kq == 0) {
        float o[8];
#pragma unroll
        for (int i = 0; i < 8; i++) o[i] = 0.f;
#pragma unroll 4
        for (int k = 0; k < 256; k++) {
            float  w  = Wo[k * 256 + gc];
            float4 hA = *reinterpret_cast<const float4*>(&hT[k * 8]);
            float4 hB = *reinterpret_cast<const float4*>(&hT[k * 8 + 4]);
            o[0] += w * hA.x;  o[1] += w * hA.y;
            o[2] += w * hA.z;  o[3] += w * hA.w;
            o[4] += w * hB.x;  o[5] += w * hB.y;
            o[6] += w * hB.z;  o[7] += w * hB.w;
        }
        float bj = bo[gc];
#pragma unroll
        for (int m = 0; m < 8; m++)
            out[(b0 + m) * 256 + gc] = o[m] + bj;
    }
}

// ---------------------------------------------------------------------------
// Launch
// ---------------------------------------------------------------------------
extern "C" void kernel_launch(void* const* d_in, const int* in_sizes, int n_in,
                              void* d_out, int out_size) {
    const float* x  = (const float*)d_in[0];
    const float* Wr = (const float*)d_in[1];
    const float* br = (const float*)d_in[2];
    const float* Wz = (const float*)d_in[3];
    const float* bz = (const float*)d_in[4];
    const float* Wh = (const float*)d_in[5];
    const float* bh = (const float*)d_in[6];
    const float* Wo = (const float*)d_in[7];
    const float* bo = (const float*)d_in[8];
    float* out = (float*)d_out;

    precompute_kernel<<<dim3(1024, 6), 256>>>(x, Wr, br, Wz, bz, Wh, bh);

    cudaFuncSetAttribute(gru_recurrence_kernel,
                         cudaFuncAttributeMaxDynamicSharedMemorySize, REC_SMEM_BYTES);

    cudaLaunchConfig_t cfg = {};
    cfg.gridDim  = dim3(128, 1, 1);
    cfg.blockDim = dim3(256, 1, 1);
    cfg.dynamicSmemBytes = REC_SMEM_BYTES;
    cfg.stream = 0;
    cudaLaunchAttribute attrs[1];
    attrs[0].id = cudaLaunchAttributeClusterDimension;
    attrs[0].val.clusterDim.x = 4;
    attrs[0].val.clusterDim.y = 1;
    attrs[0].val.clusterDim.z = 1;
    cfg.attrs = attrs;
    cfg.numAttrs = 1;
    cudaLaunchKernelEx(&cfg, gru_recurrence_kernel, Wr, Wz, Wh, Wo, bo, out);
}

// round 11
// speedup vs baseline: 2.1506x; 1.0821x over previous
#include <cuda_runtime.h>
#include <cstdint>
#include <math.h>

#define BATCH 256
#define SEQ   512
#define HID   256
#define GATE3 768

// smem floats: Ur/Uz/Uh 3*16384 + hT 2048 + rhT 2048 + z 512 + red 4096
#define REC_SMEM_FLOATS (16384*3 + 2048 + 2048 + 512 + 4096)
#define REC_SMEM_BYTES  (REC_SMEM_FLOATS * 4)   // 231424 <= 232448

// Scratch (device global: sanctioned allocation-free scratch)
__device__ float g_A[SEQ * BATCH * GATE3];  // x@W_x + bias, [t][b][gate*256+j]

// ---------------------------------------------------------------------------
// helpers
// ---------------------------------------------------------------------------
__device__ __forceinline__ uint32_t smem_u32(const void* p) {
    uint32_t a;
    asm("{ .reg .u64 t; cvta.to.shared.u64 t, %1; cvt.u32.u64 %0, t; }"
        : "=r"(a) : "l"(p));
    return a;
}
__device__ __forceinline__ uint32_t mapa_peer(uint32_t addr, uint32_t rank) {
    uint32_t r;
    asm("mapa.shared::cluster.u32 %0, %1, %2;" : "=r"(r) : "r"(addr), "r"(rank));
    return r;
}
__device__ __forceinline__ void st_cluster_v2(uint32_t addr, float2 v) {
    asm volatile("st.shared::cluster.v2.f32 [%0], {%1,%2};"
                 :: "r"(addr), "f"(v.x), "f"(v.y) : "memory");
}
__device__ __forceinline__ void st_cluster_f32(uint32_t addr, float v) {
    asm volatile("st.shared::cluster.f32 [%0], %1;"
                 :: "r"(addr), "f"(v) : "memory");
}
__device__ __forceinline__ void cluster_sync_() {
    asm volatile("barrier.cluster.arrive.aligned;" ::: "memory");
    asm volatile("barrier.cluster.wait.aligned;" ::: "memory");
}
__device__ __forceinline__ float sigmoidf_(float v) { return 1.0f / (1.0f + expf(-v)); }

// ---- packed f32x2 (used only in the precompute GEMM) ----
__device__ __forceinline__ unsigned long long packf2(float lo, float hi) {
    unsigned long long r;
    asm("mov.b64 %0, {%1, %2};" : "=l"(r)
        : "r"(__float_as_uint(lo)), "r"(__float_as_uint(hi)));
    return r;
}
__device__ __forceinline__ unsigned long long dupf2(float v) {
    unsigned long long r;
    uint32_t u = __float_as_uint(v);
    asm("mov.b64 %0, {%1, %1};" : "=l"(r) : "r"(u));
    return r;
}
__device__ __forceinline__ void ffma2(unsigned long long& d,
                                      unsigned long long a,
                                      unsigned long long b) {
    asm("fma.rn.f32x2 %0, %1, %2, %0;" : "+l"(d) : "l"(a), "l"(b));
}
__device__ __forceinline__ float2 unpackf2(unsigned long long v) {
    uint32_t lo, hi;
    asm("mov.b64 {%0, %1}, %2;" : "=r"(lo), "=r"(hi) : "l"(v));
    float2 f;
    f.x = __uint_as_float(lo);
    f.y = __uint_as_float(hi);
    return f;
}

// ---------------------------------------------------------------------------
// Precompute GEMM (unchanged, passing): g_A = x @ W_x + bias
// ---------------------------------------------------------------------------
__global__ void __launch_bounds__(256)
precompute_kernel(const float* __restrict__ x,
                  const float* __restrict__ Wr, const float* __restrict__ br,
                  const float* __restrict__ Wz, const float* __restrict__ bz,
                  const float* __restrict__ Wh, const float* __restrict__ bh) {
    __shared__ float As[16][128];
    __shared__ float Bs[16][128];

    const int by = blockIdx.y;
    const float* W;  const float* bias;
    if (by < 2)      { W = Wr; bias = br; }
    else if (by < 4) { W = Wz; bias = bz; }
    else             { W = Wh; bias = bh; }
    const int cb = (by & 1) * 128;
    const int rowBase = blockIdx.x * 128;

    const int tid = threadIdx.x;
    const int tx = tid & 15;
    const int ty = tid >> 4;

    unsigned long long acc2[8][4];
#pragma unroll
    for (int i = 0; i < 8; i++)
#pragma unroll
        for (int j = 0; j < 4; j++) acc2[i][j] = 0ull;

    for (int k0 = 0; k0 < 256; k0 += 16) {
#pragma unroll
        for (int it = 0; it < 2; it++) {
            int idx = tid * 2 + it;
            int m   = idx >> 2;
            int k4  = (idx & 3) * 4;
            int row = rowBase + m;
            int b   = row & 255;
            int t   = row >> 8;
            float4 v = *reinterpret_cast<const float4*>(
                &x[(size_t)b * (SEQ * 256) + t * 256 + k0 + k4]);
            As[k4 + 0][m] = v.x;
            As[k4 + 1][m] = v.y;
            As[k4 + 2][m] = v.z;
            As[k4 + 3][m] = v.w;
        }
#pragma unroll
        for (int it = 0; it < 2; it++) {
            int idx = tid * 2 + it;
            int kk  = idx >> 5;
            int n4  = (idx & 31) * 4;
            *reinterpret_cast<float4*>(&Bs[kk][n4]) =
                *reinterpret_cast<const float4*>(&W[(k0 + kk) * 256 + cb + n4]);
        }
        __syncthreads();

#pragma unroll
        for (int kk = 0; kk < 16; kk++) {
            float4 a0 = *reinterpret_cast<const float4*>(&As[kk][ty * 4]);
            float4 a1 = *reinterpret_cast<const float4*>(&As[kk][64 + ty * 4]);
            float4 b0 = *reinterpret_cast<const float4*>(&Bs[kk][tx * 4]);
            float4 b1 = *reinterpret_cast<const float4*>(&Bs[kk][64 + tx * 4]);
            unsigned long long bp0 = packf2(b0.x, b0.y);
            unsigned long long bp1 = packf2(b0.z, b0.w);
            unsigned long long bp2 = packf2(b1.x, b1.y);
            unsigned long long bp3 = packf2(b1.z, b1.w);
            float av[8] = {a0.x, a0.y, a0.z, a0.w, a1.x, a1.y, a1.z, a1.w};
#pragma unroll
            for (int i = 0; i < 8; i++) {
                unsigned long long ad = dupf2(av[i]);
                ffma2(acc2[i][0], ad, bp0);
                ffma2(acc2[i][1], ad, bp1);
                ffma2(acc2[i][2], ad, bp2);
                ffma2(acc2[i][3], ad, bp3);
            }
        }
        __syncthreads();
    }

#pragma unroll
    for (int i = 0; i < 8; i++) {
        int m   = (i < 4) ? (ty * 4 + i) : (64 + ty * 4 + (i - 4));
        int row = rowBase + m;
        size_t base = (size_t)row * GATE3 + by * 128;
#pragma unroll
        for (int half = 0; half < 2; half++) {
            int ncol = half * 64 + tx * 4;
            float2 p0 = unpackf2(acc2[i][half * 2 + 0]);
            float2 p1 = unpackf2(acc2[i][half * 2 + 1]);
            float4 v;
            v.x = p0.x + bias[cb + ncol + 0];
            v.y = p0.y + bias[cb + ncol + 1];
            v.z = p1.x + bias[cb + ncol + 2];
            v.w = p1.y + bias[cb + ncol + 3];
            *reinterpret_cast<float4*>(&g_A[base + ncol]) = v;
        }
    }
}

// ---------------------------------------------------------------------------
// Recurrence: 32 clusters x 4 CTAs x 512 threads. CTA rank q owns cols
// [q*64, q*64+64); cluster = 8 batch rows; state hT/rhT = [col][8 rows].
// Phase1 main: thread (jj, g, ks<4): 64-k slice, 8 rows per weight load.
// Phase2 main: thread (c, kq<8): 32-k slice, 8 rows.
// All threads write partials to red[tid*8]; epilogues remapped so ALL 512
// threads share the MUFU + remote-store work.
// ---------------------------------------------------------------------------
__global__ void __launch_bounds__(512, 1)
gru_recurrence_kernel(const float* __restrict__ Wr,
                      const float* __restrict__ Wz,
                      const float* __restrict__ Wh,
                      const float* __restrict__ Wo,
                      const float* __restrict__ bo,
                      float* __restrict__ out) {
    extern __shared__ float sm[];
    float* Ur_s = sm;                    // [256][64]
    float* Uz_s = Ur_s + 16384;
    float* Uh_s = Uz_s + 16384;
    float* hT   = Uh_s + 16384;          // [256 cols][8 rows]
    float* rhT  = hT + 2048;             // [256 cols][8 rows]
    float* z_s  = rhT + 2048;            // [64 cols][8 rows]
    float* red  = z_s + 512;             // [512 threads][8]

    const int tid = threadIdx.x;
    const int q   = blockIdx.x & 3;
    const int b0  = (blockIdx.x >> 2) * 8;

    // phase-1 main mapping
    const int jj = tid & 63;
    const int g  = (tid >> 6) & 1;
    const int ks = tid >> 7;             // 0..3, 64-k slice
    // phase-2 main mapping
    const int c  = tid & 63;
    const int kq = tid >> 6;             // 0..7, 32-k slice

    // phase-1 EPILOGUE mapping: (eg, ejj, emp) -> rows 2emp, 2emp+1
    const int eg  = tid >> 8;            // 0..1
    const int ejj = (tid >> 2) & 63;
    const int emp = tid & 3;
    const int em0 = emp * 2;
    const int ejg = q * 64 + ejj;
    // phase-2 EPILOGUE mapping: (ec, em) -> one (col,row)
    const int ec  = tid >> 3;            // 0..63
    const int em  = tid & 7;
    const int egc = q * 64 + ec;

    // ---- preload weight quarters ----
    for (int i = tid; i < 16384; i += 512) {
        int k = i >> 6, cc = i & 63;
        int gi = (256 + k) * 256 + q * 64 + cc;
        Ur_s[i] = Wr[gi];
        Uz_s[i] = Wz[gi];
        Uh_s[i] = Wh[gi];
    }
    for (int i = tid; i < 2048; i += 512) hT[i] = 0.f;
    __syncthreads();

    const float* __restrict__ Ug = g ? Uz_s : Ur_s;
    const int k1_0 = ks * 64;
    const int k2_0 = kq * 32;

    // remote peer addresses (epilogue mappings)
    const uint32_t rh_loc = smem_u32(&rhT[ejg * 8 + em0]);   // float2
    const uint32_t h_loc  = smem_u32(&hT[egc * 8 + em]);     // float
    uint32_t rh_p[3], h_p[3];
#pragma unroll
    for (int i = 0; i < 3; i++) {
        rh_p[i] = mapa_peer(rh_loc, q ^ (i + 1));
        h_p[i]  = mapa_peer(h_loc,  q ^ (i + 1));
    }

    cluster_sync_();

    for (int t = 0; t < SEQ; t++) {
        const float* __restrict__ Arow = g_A + ((size_t)t * 256 + b0) * GATE3;

        // prefetch activations for the epilogue mappings (DRAM, consumed late)
        float a_g0 = Arow[(em0 + 0) * GATE3 + eg * 256 + ejg];
        float a_g1 = Arow[(em0 + 1) * GATE3 + eg * 256 + ejg];
        float a_h  = Arow[em * GATE3 + 512 + egc];

        // ---- phase 1 main: gate pre-act, col jj gate g, 8 rows, 64-k ----
        {
            float acc[8];
#pragma unroll
            for (int i = 0; i < 8; i++) acc[i] = 0.f;
#pragma unroll 4
            for (int kk = 0; kk < 64; kk++) {
                int k = k1_0 + kk;
                float  u  = Ug[k * 64 + jj];
                float4 hA = *reinterpret_cast<const float4*>(&hT[k * 8]);
                float4 hB = *reinterpret_cast<const float4*>(&hT[k * 8 + 4]);
                acc[0] += u * hA.x;  acc[1] += u * hA.y;
                acc[2] += u * hA.z;  acc[3] += u * hA.w;
                acc[4] += u * hB.x;  acc[5] += u * hB.y;
                acc[6] += u * hB.z;  acc[7] += u * hB.w;
            }
            float* rd = &red[tid * 8];
            *reinterpret_cast<float4*>(rd)     = make_float4(acc[0], acc[1], acc[2], acc[3]);
            *reinterpret_cast<float4*>(rd + 4) = make_float4(acc[4], acc[5], acc[6], acc[7]);
        }
        __syncthreads();

        // ---- phase 1 epilogue: (eg, ejj, rows em0..em0+1), all 512 threads ----
        {
            float s0 = 0.f, s1 = 0.f;
#pragma unroll
            for (int p = 0; p < 4; p++) {
                float2 pr = *reinterpret_cast<const float2*>(
                    &red[(p * 128 + eg * 64 + ejj) * 8 + em0]);
                s0 += pr.x;
                s1 += pr.y;
            }
            if (eg == 0) {
                float2 hm = *reinterpret_cast<const float2*>(&hT[ejg * 8 + em0]);
                float2 rhv;
                rhv.x = sigmoidf_(a_g0 + s0) * hm.x;
                rhv.y = sigmoidf_(a_g1 + s1) * hm.y;
                *reinterpret_cast<float2*>(&rhT[ejg * 8 + em0]) = rhv;
                st_cluster_v2(rh_p[0], rhv);
                st_cluster_v2(rh_p[1], rhv);
                st_cluster_v2(rh_p[2], rhv);
            } else {
                float2 zv;
                zv.x = sigmoidf_(a_g0 + s0);
                zv.y = sigmoidf_(a_g1 + s1);
                *reinterpret_cast<float2*>(&z_s[ejj * 8 + em0]) = zv;
            }
        }

        cluster_sync_();   // (A) full rh visible cluster-wide; z local

        // ---- phase 2 main: h_cand pre-act, col c, 8 rows, 32-k ----
        {
            float ach[8];
#pragma unroll
            for (int i = 0; i < 8; i++) ach[i] = 0.f;
#pragma unroll 4
            for (int kk = 0; kk < 32; kk++) {
                int k = k2_0 + kk;
                float  u  = Uh_s[k * 64 + c];
                float4 rA = *reinterpret_cast<const float4*>(&rhT[k * 8]);
                float4 rB = *reinterpret_cast<const float4*>(&rhT[k * 8 + 4]);
                ach[0] += u * rA.x;  ach[1] += u * rA.y;
                ach[2] += u * rA.z;  ach[3] += u * rA.w;
                ach[4] += u * rB.x;  ach[5] += u * rB.y;
                ach[6] += u * rB.z;  ach[7] += u * rB.w;
            }
            float* rd = &red[tid * 8];
            *reinterpret_cast<float4*>(rd)     = make_float4(ach[0], ach[1], ach[2], ach[3]);
            *reinterpret_cast<float4*>(rd + 4) = make_float4(ach[4], ach[5], ach[6], ach[7]);
        }
        __syncthreads();

        // ---- phase 2 epilogue: (ec, em), all 512 threads ----
        {
            float s = 0.f;
#pragma unroll
            for (int p = 0; p < 8; p++)
                s += red[(p * 64 + ec) * 8 + em];
            float z  = z_s[ec * 8 + em];
            float ho = hT[egc * 8 + em];
            float hc = tanhf(a_h + s);
            float hn = z * ho + (1.f - z) * hc;
            hT[egc * 8 + em] = hn;
            st_cluster_f32(h_p[0], hn);
            st_cluster_f32(h_p[1], hn);
            st_cluster_f32(h_p[2], hn);
        }

        cluster_sync_();   // (B) full updated h visible before next step
    }

    // ---- fused output: out[b0+em, egc] = h_last[em] @ Wo[:, egc] + bo ----
    {
        float o = 0.f;
#pragma unroll 8
        for (int k = 0; k < 256; k++)
            o += hT[k * 8 + em] * Wo[k * 256 + egc];
        out[(b0 + em) * 256 + egc] = o + bo[egc];
    }
}

// ---------------------------------------------------------------------------
// Launch
// ---------------------------------------------------------------------------
extern "C" void kernel_launch(void* const* d_in, const int* in_sizes, int n_in,
                              void* d_out, int out_size) {
    const float* x  = (const float*)d_in[0];
    const float* Wr = (const float*)d_in[1];
    const float* br = (const float*)d_in[2];
    const float* Wz = (const float*)d_in[3];
    const float* bz = (const float*)d_in[4];
    const float* Wh = (const float*)d_in[5];
    const float* bh = (const float*)d_in[6];
    const float* Wo = (const float*)d_in[7];
    const float* bo = (const float*)d_in[8];
    float* out = (float*)d_out;

    precompute_kernel<<<dim3(1024, 6), 256>>>(x, Wr, br, Wz, bz, Wh, bh);

    cudaFuncSetAttribute(gru_recurrence_kernel,
                         cudaFuncAttributeMaxDynamicSharedMemorySize, REC_SMEM_BYTES);

    cudaLaunchConfig_t cfg = {};
    cfg.gridDim  = dim3(128, 1, 1);
    cfg.blockDim = dim3(512, 1, 1);
    cfg.dynamicSmemBytes = REC_SMEM_BYTES;
    cfg.stream = 0;
    cudaLaunchAttribute attrs[1];
    attrs[0].id = cudaLaunchAttributeClusterDimension;
    attrs[0].val.clusterDim.x = 4;
    attrs[0].val.clusterDim.y = 1;
    attrs[0].val.clusterDim.z = 1;
    cfg.attrs = attrs;
    cfg.numAttrs = 1;
    cudaLaunchKernelEx(&cfg, gru_recurrence_kernel, Wr, Wz, Wh, Wo, bo, out);
}

// round 12
// speedup vs baseline: 2.3332x; 1.0849x over previous
#include <cuda_runtime.h>
#include <cstdint>
#include <math.h>

#define BATCH 256
#define SEQ   512
#define HID   256
#define GATE3 768

// smem floats: Urz(float2)[256][64]=32768 + Uh 16384 + hT 2048 + rhT 2048
//            + z 512 + red 4096  => 57856 floats = 231424 B <= 232448
#define REC_SMEM_FLOATS (32768 + 16384 + 2048 + 2048 + 512 + 4096)
#define REC_SMEM_BYTES  (REC_SMEM_FLOATS * 4)

// Scratch (device global: sanctioned allocation-free scratch)
__device__ float g_A[SEQ * BATCH * GATE3];  // x@W_x + bias, [t][b][gate*256+j]

// ---------------------------------------------------------------------------
// helpers
// ---------------------------------------------------------------------------
__device__ __forceinline__ uint32_t smem_u32(const void* p) {
    uint32_t a;
    asm("{ .reg .u64 t; cvta.to.shared.u64 t, %1; cvt.u32.u64 %0, t; }"
        : "=r"(a) : "l"(p));
    return a;
}
__device__ __forceinline__ uint32_t mapa_peer(uint32_t addr, uint32_t rank) {
    uint32_t r;
    asm("mapa.shared::cluster.u32 %0, %1, %2;" : "=r"(r) : "r"(addr), "r"(rank));
    return r;
}
__device__ __forceinline__ void st_cluster_f32(uint32_t addr, float v) {
    asm volatile("st.shared::cluster.f32 [%0], %1;"
                 :: "r"(addr), "f"(v) : "memory");
}
__device__ __forceinline__ void cluster_sync_() {
    asm volatile("barrier.cluster.arrive.aligned;" ::: "memory");
    asm volatile("barrier.cluster.wait.aligned;" ::: "memory");
}
__device__ __forceinline__ float sigmoidf_(float v) { return 1.0f / (1.0f + expf(-v)); }

// ---- packed f32x2 (used only in the precompute GEMM) ----
__device__ __forceinline__ unsigned long long packf2(float lo, float hi) {
    unsigned long long r;
    asm("mov.b64 %0, {%1, %2};" : "=l"(r)
        : "r"(__float_as_uint(lo)), "r"(__float_as_uint(hi)));
    return r;
}
__device__ __forceinline__ unsigned long long dupf2(float v) {
    unsigned long long r;
    uint32_t u = __float_as_uint(v);
    asm("mov.b64 %0, {%1, %1};" : "=l"(r) : "r"(u));
    return r;
}
__device__ __forceinline__ void ffma2(unsigned long long& d,
                                      unsigned long long a,
                                      unsigned long long b) {
    asm("fma.rn.f32x2 %0, %1, %2, %0;" : "+l"(d) : "l"(a), "l"(b));
}
__device__ __forceinline__ float2 unpackf2(unsigned long long v) {
    uint32_t lo, hi;
    asm("mov.b64 {%0, %1}, %2;" : "=r"(lo), "=r"(hi) : "l"(v));
    float2 f;
    f.x = __uint_as_float(lo);
    f.y = __uint_as_float(hi);
    return f;
}

// ---------------------------------------------------------------------------
// Precompute GEMM (unchanged, near FFMA2 roofline): g_A = x @ W_x + bias
// ---------------------------------------------------------------------------
__global__ void __launch_bounds__(256)
precompute_kernel(const float* __restrict__ x,
                  const float* __restrict__ Wr, const float* __restrict__ br,
                  const float* __restrict__ Wz, const float* __restrict__ bz,
                  const float* __restrict__ Wh, const float* __restrict__ bh) {
    __shared__ float As[16][128];
    __shared__ float Bs[16][128];

    const int by = blockIdx.y;
    const float* W;  const float* bias;
    if (by < 2)      { W = Wr; bias = br; }
    else if (by < 4) { W = Wz; bias = bz; }
    else             { W = Wh; bias = bh; }
    const int cb = (by & 1) * 128;
    const int rowBase = blockIdx.x * 128;

    const int tid = threadIdx.x;
    const int tx = tid & 15;
    const int ty = tid >> 4;

    unsigned long long acc2[8][4];
#pragma unroll
    for (int i = 0; i < 8; i++)
#pragma unroll
        for (int j = 0; j < 4; j++) acc2[i][j] = 0ull;

    for (int k0 = 0; k0 < 256; k0 += 16) {
#pragma unroll
        for (int it = 0; it < 2; it++) {
            int idx = tid * 2 + it;
            int m   = idx >> 2;
            int k4  = (idx & 3) * 4;
            int row = rowBase + m;
            int b   = row & 255;
            int t   = row >> 8;
            float4 v = *reinterpret_cast<const float4*>(
                &x[(size_t)b * (SEQ * 256) + t * 256 + k0 + k4]);
            As[k4 + 0][m] = v.x;
            As[k4 + 1][m] = v.y;
            As[k4 + 2][m] = v.z;
            As[k4 + 3][m] = v.w;
        }
#pragma unroll
        for (int it = 0; it < 2; it++) {
            int idx = tid * 2 + it;
            int kk  = idx >> 5;
            int n4  = (idx & 31) * 4;
            *reinterpret_cast<float4*>(&Bs[kk][n4]) =
                *reinterpret_cast<const float4*>(&W[(k0 + kk) * 256 + cb + n4]);
        }
        __syncthreads();

#pragma unroll
        for (int kk = 0; kk < 16; kk++) {
            float4 a0 = *reinterpret_cast<const float4*>(&As[kk][ty * 4]);
            float4 a1 = *reinterpret_cast<const float4*>(&As[kk][64 + ty * 4]);
            float4 b0 = *reinterpret_cast<const float4*>(&Bs[kk][tx * 4]);
            float4 b1 = *reinterpret_cast<const float4*>(&Bs[kk][64 + tx * 4]);
            unsigned long long bp0 = packf2(b0.x, b0.y);
            unsigned long long bp1 = packf2(b0.z, b0.w);
            unsigned long long bp2 = packf2(b1.x, b1.y);
            unsigned long long bp3 = packf2(b1.z, b1.w);
            float av[8] = {a0.x, a0.y, a0.z, a0.w, a1.x, a1.y, a1.z, a1.w};
#pragma unroll
            for (int i = 0; i < 8; i++) {
                unsigned long long ad = dupf2(av[i]);
                ffma2(acc2[i][0], ad, bp0);
                ffma2(acc2[i][1], ad, bp1);
                ffma2(acc2[i][2], ad, bp2);
                ffma2(acc2[i][3], ad, bp3);
            }
        }
        __syncthreads();
    }

#pragma unroll
    for (int i = 0; i < 8; i++) {
        int m   = (i < 4) ? (ty * 4 + i) : (64 + ty * 4 + (i - 4));
        int row = rowBase + m;
        size_t base = (size_t)row * GATE3 + by * 128;
#pragma unroll
        for (int half = 0; half < 2; half++) {
            int ncol = half * 64 + tx * 4;
            float2 p0 = unpackf2(acc2[i][half * 2 + 0]);
            float2 p1 = unpackf2(acc2[i][half * 2 + 1]);
            float4 v;
            v.x = p0.x + bias[cb + ncol + 0];
            v.y = p0.y + bias[cb + ncol + 1];
            v.z = p1.x + bias[cb + ncol + 2];
            v.w = p1.y + bias[cb + ncol + 3];
            *reinterpret_cast<float4*>(&g_A[base + ncol]) = v;
        }
    }
}

// ---------------------------------------------------------------------------
// Recurrence: 32 clusters x 4 CTAs x 512 threads. CTA rank q owns cols
// [q*64, q*64+64); cluster = 8 batch rows; state hT/rhT = [col][8 rows].
// Phase1 main: thread (jj, ks<8): BOTH gates (Urz float2), 8 rows, 32-k slice
//   per k: LDS.64 w + 2x LDS.128 broadcast h = 4 wf for 16 MACs.
// Sequential r / z / h reductions through one 16KB red buffer; all epilogues
// use the uniform (ec, em) = (col, row) mapping over all 512 threads.
// ---------------------------------------------------------------------------
__global__ void __launch_bounds__(512, 1)
gru_recurrence_kernel(const float* __restrict__ Wr,
                      const float* __restrict__ Wz,
                      const float* __restrict__ Wh,
                      const float* __restrict__ Wo,
                      const float* __restrict__ bo,
                      float* __restrict__ out) {
    extern __shared__ float sm[];
    float2* Urz = (float2*)sm;            // [256][64] (k, col) -> (Ur, Uz)
    float*  Uh_s = sm + 32768;            // [256][64]
    float*  hT   = Uh_s + 16384;          // [256 cols][8 rows]
    float*  rhT  = hT + 2048;             // [256 cols][8 rows]
    float*  z_s  = rhT + 2048;            // [64 cols * 8 rows] = [tid]
    float*  red  = z_s + 512;             // [512 threads][8]

    const int tid = threadIdx.x;
    const int q   = blockIdx.x & 3;
    const int b0  = (blockIdx.x >> 2) * 8;

    // phase-1 main mapping: column jj, 32-k slice ks
    const int jj = tid & 63;
    const int ks = tid >> 6;             // 0..7
    const int k1_0 = ks * 32;
    // phase-2 main mapping: column c, 32-k slice kq
    const int c  = tid & 63;
    const int kq = tid >> 6;             // 0..7
    const int k2_0 = kq * 32;
    // uniform epilogue mapping: (col ec, row em); note tid == ec*8+em
    const int ec  = tid >> 3;            // 0..63
    const int em  = tid & 7;
    const int egc = q * 64 + ec;

    // ---- preload weight quarters ----
    for (int i = tid; i < 16384; i += 512) {
        int k = i >> 6, cc = i & 63;
        int gi = (256 + k) * 256 + q * 64 + cc;
        Urz[i]  = make_float2(Wr[gi], Wz[gi]);
        Uh_s[i] = Wh[gi];
    }
    for (int i = tid; i < 2048; i += 512) hT[i] = 0.f;
    __syncthreads();

    // remote peer addresses (epilogue mapping)
    const uint32_t rh_loc = smem_u32(&rhT[egc * 8 + em]);
    const uint32_t h_loc  = smem_u32(&hT[egc * 8 + em]);
    uint32_t rh_p[3], h_p[3];
#pragma unroll
    for (int i = 0; i < 3; i++) {
        rh_p[i] = mapa_peer(rh_loc, q ^ (i + 1));
        h_p[i]  = mapa_peer(h_loc,  q ^ (i + 1));
    }

    cluster_sync_();

    for (int t = 0; t < SEQ; t++) {
        const float* __restrict__ Arow = g_A + ((size_t)t * 256 + b0) * GATE3;

        // prefetch activations for the uniform epilogue target (DRAM)
        float a_r = Arow[em * GATE3 + egc];
        float a_z = Arow[em * GATE3 + 256 + egc];
        float a_h = Arow[em * GATE3 + 512 + egc];

        // ---- phase 1 main: both gates, col jj, 8 rows, 32-k slice ----
        float accr[8], accz[8];
#pragma unroll
        for (int i = 0; i < 8; i++) { accr[i] = 0.f; accz[i] = 0.f; }
#pragma unroll 4
        for (int kk = 0; kk < 32; kk++) {
            int k = k1_0 + kk;
            float2 u  = Urz[k * 64 + jj];
            float4 hA = *reinterpret_cast<const float4*>(&hT[k * 8]);
            float4 hB = *reinterpret_cast<const float4*>(&hT[k * 8 + 4]);
            accr[0] += u.x * hA.x;  accz[0] += u.y * hA.x;
            accr[1] += u.x * hA.y;  accz[1] += u.y * hA.y;
            accr[2] += u.x * hA.z;  accz[2] += u.y * hA.z;
            accr[3] += u.x * hA.w;  accz[3] += u.y * hA.w;
            accr[4] += u.x * hB.x;  accz[4] += u.y * hB.x;
            accr[5] += u.x * hB.y;  accz[5] += u.y * hB.y;
            accr[6] += u.x * hB.z;  accz[6] += u.y * hB.z;
            accr[7] += u.x * hB.w;  accz[7] += u.y * hB.w;
        }

        // r-pass: store partials, reduce, rh -> local + 3 peers
        *reinterpret_cast<float4*>(&red[tid * 8]) =
            make_float4(accr[0], accr[1], accr[2], accr[3]);
        *reinterpret_cast<float4*>(&red[tid * 8 + 4]) =
            make_float4(accr[4], accr[5], accr[6], accr[7]);
        __syncthreads();                             // S1
        {
            float s = 0.f;
#pragma unroll
            for (int p = 0; p < 8; p++) s += red[p * 512 + tid];
            float ho = hT[egc * 8 + em];
            float rh = sigmoidf_(a_r + s) * ho;
            rhT[egc * 8 + em] = rh;
            st_cluster_f32(rh_p[0], rh);
            st_cluster_f32(rh_p[1], rh);
            st_cluster_f32(rh_p[2], rh);
        }
        cluster_sync_();   // (A) rh visible cluster-wide; also protects red reuse

        // z-pass: store partials, reduce into z_s (local only)
        *reinterpret_cast<float4*>(&red[tid * 8]) =
            make_float4(accz[0], accz[1], accz[2], accz[3]);
        *reinterpret_cast<float4*>(&red[tid * 8 + 4]) =
            make_float4(accz[4], accz[5], accz[6], accz[7]);
        __syncthreads();                             // S2
        {
            float s = 0.f;
#pragma unroll
            for (int p = 0; p < 8; p++) s += red[p * 512 + tid];
            z_s[tid] = sigmoidf_(a_z + s);
        }

        // ---- phase 2 main: h_cand pre-act, col c, 8 rows, 32-k slice ----
        float ach[8];
#pragma unroll
        for (int i = 0; i < 8; i++) ach[i] = 0.f;
#pragma unroll 4
        for (int kk = 0; kk < 32; kk++) {
            int k = k2_0 + kk;
            float  u  = Uh_s[k * 64 + c];
            float4 rA = *reinterpret_cast<const float4*>(&rhT[k * 8]);
            float4 rB = *reinterpret_cast<const float4*>(&rhT[k * 8 + 4]);
            ach[0] += u * rA.x;  ach[1] += u * rA.y;
            ach[2] += u * rA.z;  ach[3] += u * rA.w;
            ach[4] += u * rB.x;  ach[5] += u * rB.y;
            ach[6] += u * rB.z;  ach[7] += u * rB.w;
        }
        __syncthreads();                             // S3: z reads of red done
        *reinterpret_cast<float4*>(&red[tid * 8]) =
            make_float4(ach[0], ach[1], ach[2], ach[3]);
        *reinterpret_cast<float4*>(&red[tid * 8 + 4]) =
            make_float4(ach[4], ach[5], ach[6], ach[7]);
        __syncthreads();                             // S4
        {
            float s = 0.f;
#pragma unroll
            for (int p = 0; p < 8; p++) s += red[p * 512 + tid];
            float z  = z_s[tid];
            float ho = hT[egc * 8 + em];
            float hc = tanhf(a_h + s);
            float hn = z * ho + (1.f - z) * hc;
            hT[egc * 8 + em] = hn;
            st_cluster_f32(h_p[0], hn);
            st_cluster_f32(h_p[1], hn);
            st_cluster_f32(h_p[2], hn);
        }

        cluster_sync_();   // (B) full updated h visible before next step
    }

    // ---- fused output: out[b0+em, egc] = h_last[em] @ Wo[:, egc] + bo ----
    {
        float o = 0.f;
#pragma unroll 8
        for (int k = 0; k < 256; k++)
            o += hT[k * 8 + em] * Wo[k * 256 + egc];
        out[(b0 + em) * 256 + egc] = o + bo[egc];
    }
}

// ---------------------------------------------------------------------------
// Launch
// ---------------------------------------------------------------------------
extern "C" void kernel_launch(void* const* d_in, const int* in_sizes, int n_in,
                              void* d_out, int out_size) {
    const float* x  = (const float*)d_in[0];
    const float* Wr = (const float*)d_in[1];
    const float* br = (const float*)d_in[2];
    const float* Wz = (const float*)d_in[3];
    const float* bz = (const float*)d_in[4];
    const float* Wh = (const float*)d_in[5];
    const float* bh = (const float*)d_in[6];
    const float* Wo = (const float*)d_in[7];
    const float* bo = (const float*)d_in[8];
    float* out = (float*)d_out;

    precompute_kernel<<<dim3(1024, 6), 256>>>(x, Wr, br, Wz, bz, Wh, bh);

    cudaFuncSetAttribute(gru_recurrence_kernel,
                         cudaFuncAttributeMaxDynamicSharedMemorySize, REC_SMEM_BYTES);

    cudaLaunchConfig_t cfg = {};
    cfg.gridDim  = dim3(128, 1, 1);
    cfg.blockDim = dim3(512, 1, 1);
    cfg.dynamicSmemBytes = REC_SMEM_BYTES;
    cfg.stream = 0;
    cudaLaunchAttribute attrs[1];
    attrs[0].id = cudaLaunchAttributeClusterDimension;
    attrs[0].val.clusterDim.x = 4;
    attrs[0].val.clusterDim.y = 1;
    attrs[0].val.clusterDim.z = 1;
    cfg.attrs = attrs;
    cfg.numAttrs = 1;
    cudaLaunchKernelEx(&cfg, gru_recurrence_kernel, Wr, Wz, Wh, Wo, bo, out);
}

// round 15
// speedup vs baseline: 2.4189x; 1.0367x over previous
#include <cuda_runtime.h>
#include <cstdint>
#include <math.h>

#define BATCH 256
#define SEQ   512
#define HID   256
#define GATE3 768

// smem floats: Urz(float2)[256][64]=32768 + Uh 16384 + hT 2048 + rhT 2048 + red 4096
#define REC_SMEM_FLOATS (32768 + 16384 + 2048 + 2048 + 4096)
#define REC_SMEM_BYTES  (REC_SMEM_FLOATS * 4)   // 229376

// Scratch (device global: sanctioned allocation-free scratch)
__device__ float g_A[SEQ * BATCH * GATE3];  // x@W_x + bias, [t][b][gate*256+j]

// ---------------------------------------------------------------------------
// helpers
// ---------------------------------------------------------------------------
__device__ __forceinline__ uint32_t smem_u32(const void* p) {
    uint32_t a;
    asm("{ .reg .u64 t; cvta.to.shared.u64 t, %1; cvt.u32.u64 %0, t; }"
        : "=r"(a) : "l"(p));
    return a;
}
__device__ __forceinline__ uint32_t mapa_peer(uint32_t addr, uint32_t rank) {
    uint32_t r;
    asm("mapa.shared::cluster.u32 %0, %1, %2;" : "=r"(r) : "r"(addr), "r"(rank));
    return r;
}
__device__ __forceinline__ void st_cluster_f32(uint32_t addr, float v) {
    asm volatile("st.shared::cluster.f32 [%0], %1;"
                 :: "r"(addr), "f"(v) : "memory");
}
__device__ __forceinline__ void cluster_sync_() {
    asm volatile("barrier.cluster.arrive.aligned;" ::: "memory");
    asm volatile("barrier.cluster.wait.aligned;" ::: "memory");
}
__device__ __forceinline__ void cluster_arrive_() {
    asm volatile("barrier.cluster.arrive.aligned;" ::: "memory");
}
__device__ __forceinline__ void cluster_wait_() {
    asm volatile("barrier.cluster.wait.aligned;" ::: "memory");
}
__device__ __forceinline__ float sigmoidf_(float v) { return 1.0f / (1.0f + expf(-v)); }

// ---- packed f32x2 (used only in the precompute GEMM) ----
__device__ __forceinline__ unsigned long long packf2(float lo, float hi) {
    unsigned long long r;
    asm("mov.b64 %0, {%1, %2};" : "=l"(r)
        : "r"(__float_as_uint(lo)), "r"(__float_as_uint(hi)));
    return r;
}
__device__ __forceinline__ unsigned long long dupf2(float v) {
    unsigned long long r;
    uint32_t u = __float_as_uint(v);
    asm("mov.b64 %0, {%1, %1};" : "=l"(r) : "r"(u));
    return r;
}
__device__ __forceinline__ void ffma2(unsigned long long& d,
                                      unsigned long long a,
                                      unsigned long long b) {
    asm("fma.rn.f32x2 %0, %1, %2, %0;" : "+l"(d) : "l"(a), "l"(b));
}
__device__ __forceinline__ float2 unpackf2(unsigned long long v) {
    uint32_t lo, hi;
    asm("mov.b64 {%0, %1}, %2;" : "=r"(lo), "=r"(hi) : "l"(v));
    float2 f;
    f.x = __uint_as_float(lo);
    f.y = __uint_as_float(hi);
    return f;
}

// ---------------------------------------------------------------------------
// Precompute GEMM (unchanged): g_A = x @ W_x + bias
// ---------------------------------------------------------------------------
__global__ void __launch_bounds__(256)
precompute_kernel(const float* __restrict__ x,
                  const float* __restrict__ Wr, const float* __restrict__ br,
                  const float* __restrict__ Wz, const float* __restrict__ bz,
                  const float* __restrict__ Wh, const float* __restrict__ bh) {
    __shared__ float As[16][128];
    __shared__ float Bs[16][128];

    const int by = blockIdx.y;
    const float* W;  const float* bias;
    if (by < 2)      { W = Wr; bias = br; }
    else if (by < 4) { W = Wz; bias = bz; }
    else             { W = Wh; bias = bh; }
    const int cb = (by & 1) * 128;
    const int rowBase = blockIdx.x * 128;

    const int tid = threadIdx.x;
    const int tx = tid & 15;
    const int ty = tid >> 4;

    unsigned long long acc2[8][4];
#pragma unroll
    for (int i = 0; i < 8; i++)
#pragma unroll
        for (int j = 0; j < 4; j++) acc2[i][j] = 0ull;

    for (int k0 = 0; k0 < 256; k0 += 16) {
#pragma unroll
        for (int it = 0; it < 2; it++) {
            int idx = tid * 2 + it;
            int m   = idx >> 2;
            int k4  = (idx & 3) * 4;
            int row = rowBase + m;
            int b   = row & 255;
            int t   = row >> 8;
            float4 v = *reinterpret_cast<const float4*>(
                &x[(size_t)b * (SEQ * 256) + t * 256 + k0 + k4]);
            As[k4 + 0][m] = v.x;
            As[k4 + 1][m] = v.y;
            As[k4 + 2][m] = v.z;
            As[k4 + 3][m] = v.w;
        }
#pragma unroll
        for (int it = 0; it < 2; it++) {
            int idx = tid * 2 + it;
            int kk  = idx >> 5;
            int n4  = (idx & 31) * 4;
            *reinterpret_cast<float4*>(&Bs[kk][n4]) =
                *reinterpret_cast<const float4*>(&W[(k0 + kk) * 256 + cb + n4]);
        }
        __syncthreads();

#pragma unroll
        for (int kk = 0; kk < 16; kk++) {
            float4 a0 = *reinterpret_cast<const float4*>(&As[kk][ty * 4]);
            float4 a1 = *reinterpret_cast<const float4*>(&As[kk][64 + ty * 4]);
            float4 b0 = *reinterpret_cast<const float4*>(&Bs[kk][tx * 4]);
            float4 b1 = *reinterpret_cast<const float4*>(&Bs[kk][64 + tx * 4]);
            unsigned long long bp0 = packf2(b0.x, b0.y);
            unsigned long long bp1 = packf2(b0.z, b0.w);
            unsigned long long bp2 = packf2(b1.x, b1.y);
            unsigned long long bp3 = packf2(b1.z, b1.w);
            float av[8] = {a0.x, a0.y, a0.z, a0.w, a1.x, a1.y, a1.z, a1.w};
#pragma unroll
            for (int i = 0; i < 8; i++) {
                unsigned long long ad = dupf2(av[i]);
                ffma2(acc2[i][0], ad, bp0);
                ffma2(acc2[i][1], ad, bp1);
                ffma2(acc2[i][2], ad, bp2);
                ffma2(acc2[i][3], ad, bp3);
            }
        }
        __syncthreads();
    }

#pragma unroll
    for (int i = 0; i < 8; i++) {
        int m   = (i < 4) ? (ty * 4 + i) : (64 + ty * 4 + (i - 4));
        int row = rowBase + m;
        size_t base = (size_t)row * GATE3 + by * 128;
#pragma unroll
        for (int half = 0; half < 2; half++) {
            int ncol = half * 64 + tx * 4;
            float2 p0 = unpackf2(acc2[i][half * 2 + 0]);
            float2 p1 = unpackf2(acc2[i][half * 2 + 1]);
            float4 v;
            v.x = p0.x + bias[cb + ncol + 0];
            v.y = p0.y + bias[cb + ncol + 1];
            v.z = p1.x + bias[cb + ncol + 2];
            v.w = p1.y + bias[cb + ncol + 3];
            *reinterpret_cast<float4*>(&g_A[base + ncol]) = v;
        }
    }
}

// ---------------------------------------------------------------------------
// Recurrence: 32 clusters x 4 CTAs x 512 threads. CTA rank q owns cols
// [q*64, q*64+64); cluster = 8 batch rows; state hT/rhT = [col][8 rows].
// Swizzled conflict-free red buffer; h and z carried in registers; split
// cluster arrive/wait to overlap barrier latency with the z-pass/prefetch.
// ---------------------------------------------------------------------------
__global__ void __launch_bounds__(512, 1)
gru_recurrence_kernel(const float* __restrict__ Wr,
                      const float* __restrict__ Wz,
                      const float* __restrict__ Wh,
                      const float* __restrict__ Wo,
                      const float* __restrict__ bo,
                      float* __restrict__ out) {
    extern __shared__ float sm[];
    float2* Urz  = (float2*)sm;           // [256][64] (k, col) -> (Ur, Uz)
    float*  Uh_s = sm + 32768;            // [256][64]
    float*  hT   = Uh_s + 16384;          // [256 cols][8 rows]
    float*  rhT  = hT + 2048;             // [256 cols][8 rows]
    float*  red  = rhT + 2048;            // [512 threads][8], swizzled

    const int tid = threadIdx.x;
    const int q   = blockIdx.x & 3;
    const int b0  = (blockIdx.x >> 2) * 8;

    // phase-1 main mapping: column jj, 32-k slice ks
    const int jj = tid & 63;
    const int ks = tid >> 6;
    const int k1_0 = ks * 32;
    // phase-2 main mapping: column c, 32-k slice kq
    const int c  = tid & 63;
    const int kq = tid >> 6;
    const int k2_0 = kq * 32;
    // uniform epilogue mapping: (col ec, row em); tid == ec*8+em
    const int ec  = tid >> 3;
    const int em  = tid & 7;
    const int egc = q * 64 + ec;

    // red swizzle: writer slot (i + (tid>>2)) & 7; reader offset (em + (ec>>2)) & 7
    int widx[8];
#pragma unroll
    for (int i = 0; i < 8; i++) widx[i] = tid * 8 + ((i + (tid >> 2)) & 7);
    const int rbase = ec * 8 + ((em + (ec >> 2)) & 7);

    // ---- preload weight quarters ----
    for (int i = tid; i < 16384; i += 512) {
        int k = i >> 6, cc = i & 63;
        int gi = (256 + k) * 256 + q * 64 + cc;
        Urz[i]  = make_float2(Wr[gi], Wz[gi]);
        Uh_s[i] = Wh[gi];
    }
    for (int i = tid; i < 2048; i += 512) hT[i] = 0.f;
    __syncthreads();

    // remote peer addresses (epilogue mapping)
    const uint32_t rh_loc = smem_u32(&rhT[egc * 8 + em]);
    const uint32_t h_loc  = smem_u32(&hT[egc * 8 + em]);
    uint32_t rh_p[3], h_p[3];
#pragma unroll
    for (int i = 0; i < 3; i++) {
        rh_p[i] = mapa_peer(rh_loc, q ^ (i + 1));
        h_p[i]  = mapa_peer(h_loc,  q ^ (i + 1));
    }

    cluster_sync_();     // init visible (gen 1)
    cluster_arrive_();   // pre-arm barrier B for first iteration

    float h_reg = 0.f;   // h[b0+em][egc] carried in register
    // prefetch t=0 activations
    const float* Ar0 = g_A + (size_t)b0 * GATE3;
    float a_r = Ar0[em * GATE3 + egc];
    float a_z = Ar0[em * GATE3 + 256 + egc];
    float a_h = Ar0[em * GATE3 + 512 + egc];

    for (int t = 0; t < SEQ; t++) {
        cluster_wait_();   // (B) all h updates visible; acts as CTA barrier

        // ---- phase 1 main: both gates, col jj, 8 rows, 32-k slice ----
        float accr[8], accz[8];
#pragma unroll
        for (int i = 0; i < 8; i++) { accr[i] = 0.f; accz[i] = 0.f; }
#pragma unroll 8
        for (int kk = 0; kk < 32; kk++) {
            int k = k1_0 + kk;
            float2 u  = Urz[k * 64 + jj];
            float4 hA = *reinterpret_cast<const float4*>(&hT[k * 8]);
            float4 hB = *reinterpret_cast<const float4*>(&hT[k * 8 + 4]);
            accr[0] += u.x * hA.x;  accz[0] += u.y * hA.x;
            accr[1] += u.x * hA.y;  accz[1] += u.y * hA.y;
            accr[2] += u.x * hA.z;  accz[2] += u.y * hA.z;
            accr[3] += u.x * hA.w;  accz[3] += u.y * hA.w;
            accr[4] += u.x * hB.x;  accz[4] += u.y * hB.x;
            accr[5] += u.x * hB.y;  accz[5] += u.y * hB.y;
            accr[6] += u.x * hB.z;  accz[6] += u.y * hB.z;
            accr[7] += u.x * hB.w;  accz[7] += u.y * hB.w;
        }

        // r-pass
#pragma unroll
        for (int i = 0; i < 8; i++) red[widx[i]] = accr[i];
        __syncthreads();                             // S1
        {
            float s = 0.f;
#pragma unroll
            for (int p = 0; p < 8; p++) s += red[p * 512 + rbase];
            float rh = sigmoidf_(a_r + s) * h_reg;
            rhT[egc * 8 + em] = rh;
            st_cluster_f32(rh_p[0], rh);
            st_cluster_f32(rh_p[1], rh);
            st_cluster_f32(rh_p[2], rh);
        }
        cluster_arrive_();                           // (A) armed; overlap z-pass
        __syncthreads();                             // S2: r reads done
        // z-pass (local only, overlaps cluster barrier A)
#pragma unroll
        for (int i = 0; i < 8; i++) red[widx[i]] = accz[i];
        __syncthreads();                             // S3
        float z_reg;
        {
            float s = 0.f;
#pragma unroll
            for (int p = 0; p < 8; p++) s += red[p * 512 + rbase];
            z_reg = sigmoidf_(a_z + s);
        }
        __syncthreads();                             // S4: z reads done
        cluster_wait_();                             // (A) all rh visible

        // ---- phase 2 main: h_cand pre-act, col c, 8 rows, 32-k slice ----
        float ach[8];
#pragma unroll
        for (int i = 0; i < 8; i++) ach[i] = 0.f;
#pragma unroll 8
        for (int kk = 0; kk < 32; kk++) {
            int k = k2_0 + kk;
            float  u  = Uh_s[k * 64 + c];
            float4 rA = *reinterpret_cast<const float4*>(&rhT[k * 8]);
            float4 rB = *reinterpret_cast<const float4*>(&rhT[k * 8 + 4]);
            ach[0] += u * rA.x;  ach[1] += u * rA.y;
            ach[2] += u * rA.z;  ach[3] += u * rA.w;
            ach[4] += u * rB.x;  ach[5] += u * rB.y;
            ach[6] += u * rB.z;  ach[7] += u * rB.w;
        }
#pragma unroll
        for (int i = 0; i < 8; i++) red[widx[i]] = ach[i];
        __syncthreads();                             // S5
        {
            float s = 0.f;
#pragma unroll
            for (int p = 0; p < 8; p++) s += red[p * 512 + rbase];
            float hc = tanhf(a_h + s);
            float hn = z_reg * h_reg + (1.f - z_reg) * hc;
            h_reg = hn;
            hT[egc * 8 + em] = hn;
            st_cluster_f32(h_p[0], hn);
            st_cluster_f32(h_p[1], hn);
            st_cluster_f32(h_p[2], hn);
        }
        cluster_arrive_();                           // (B) armed; overlap prefetch

        // prefetch next step's activations (wrap on last iter; values unused)
        {
            int t2 = (t + 1 < SEQ) ? (t + 1) : 0;
            const float* An = g_A + ((size_t)t2 * 256 + b0) * GATE3;
            a_r = An[em * GATE3 + egc];
            a_z = An[em * GATE3 + 256 + egc];
            a_h = An[em * GATE3 + 512 + egc];
        }
    }
    cluster_wait_();   // final h from all peers visible

    // ---- fused output: out[b0+em, egc] = h_last[em] @ Wo[:, egc] + bo ----
    {
        float o = 0.f;
#pragma unroll 8
        for (int k = 0; k < 256; k++)
            o += hT[k * 8 + em] * Wo[k * 256 + egc];
        out[(b0 + em) * 256 + egc] = o + bo[egc];
    }
}

// ---------------------------------------------------------------------------
// Launch
// ---------------------------------------------------------------------------
extern "C" void kernel_launch(void* const* d_in, const int* in_sizes, int n_in,
                              void* d_out, int out_size) {
    const float* x  = (const float*)d_in[0];
    const float* Wr = (const float*)d_in[1];
    const float* br = (const float*)d_in[2];
    const float* Wz = (const float*)d_in[3];
    const float* bz = (const float*)d_in[4];
    const float* Wh = (const float*)d_in[5];
    const float* bh = (const float*)d_in[6];
    const float* Wo = (const float*)d_in[7];
    const float* bo = (const float*)d_in[8];
    float* out = (float*)d_out;

    precompute_kernel<<<dim3(1024, 6), 256>>>(x, Wr, br, Wz, bz, Wh, bh);

    cudaFuncSetAttribute(gru_recurrence_kernel,
                         cudaFuncAttributeMaxDynamicSharedMemorySize, REC_SMEM_BYTES);

    cudaLaunchConfig_t cfg = {};
    cfg.gridDim  = dim3(128, 1, 1);
    cfg.blockDim = dim3(512, 1, 1);
    cfg.dynamicSmemBytes = REC_SMEM_BYTES;
    cfg.stream = 0;
    cudaLaunchAttribute attrs[1];
    attrs[0].id = cudaLaunchAttributeClusterDimension;
    attrs[0].val.clusterDim.x = 4;
    attrs[0].val.clusterDim.y = 1;
    attrs[0].val.clusterDim.z = 1;
    cfg.attrs = attrs;
    cfg.numAttrs = 1;
    cudaLaunchKernelEx(&cfg, gru_recurrence_kernel, Wr, Wz, Wh, Wo, bo, out);
}

// round 17
// speedup vs baseline: 2.7763x; 1.1477x over previous
#include <cuda_runtime.h>
#include <cuda_bf16.h>
#include <cstdint>
#include <math.h>

#define BATCH 256
#define SEQ   512
#define HID   256
#define GATE3 768

// ---- recurrence smem (unchanged from best kernel) ----
#define REC_SMEM_FLOATS (32768 + 16384 + 2048 + 2048 + 4096)
#define REC_SMEM_BYTES  (REC_SMEM_FLOATS * 4)   // 229376

// ---- scratch device globals ----
__device__ float g_A[SEQ * BATCH * GATE3];          // x@W_x + bias, [t*256+b][gate*256+j]
__device__ __nv_bfloat16 g_xhi[SEQ * BATCH * 256];  // [m][k] hi plane
__device__ __nv_bfloat16 g_xlo[SEQ * BATCH * 256];  // [m][k] lo plane
__device__ __nv_bfloat16 g_Whi[GATE3 * 256];        // [n][k] hi plane (W^T)
__device__ __nv_bfloat16 g_Wlo[GATE3 * 256];        // [n][k] lo plane

// ---------------------------------------------------------------------------
// generic helpers
// ---------------------------------------------------------------------------
__device__ __forceinline__ uint32_t smem_u32(const void* p) {
    uint32_t a;
    asm("{ .reg .u64 t; cvta.to.shared.u64 t, %1; cvt.u32.u64 %0, t; }"
        : "=r"(a) : "l"(p));
    return a;
}
__device__ __forceinline__ uint32_t mapa_peer(uint32_t addr, uint32_t rank) {
    uint32_t r;
    asm("mapa.shared::cluster.u32 %0, %1, %2;" : "=r"(r) : "r"(addr), "r"(rank));
    return r;
}
__device__ __forceinline__ void st_cluster_f32(uint32_t addr, float v) {
    asm volatile("st.shared::cluster.f32 [%0], %1;" :: "r"(addr), "f"(v) : "memory");
}
__device__ __forceinline__ void cluster_sync_() {
    asm volatile("barrier.cluster.arrive.aligned;" ::: "memory");
    asm volatile("barrier.cluster.wait.aligned;" ::: "memory");
}
__device__ __forceinline__ void cluster_arrive_() {
    asm volatile("barrier.cluster.arrive.aligned;" ::: "memory");
}
__device__ __forceinline__ void cluster_wait_() {
    asm volatile("barrier.cluster.wait.aligned;" ::: "memory");
}
__device__ __forceinline__ float sigmoidf_(float v) { return 1.0f / (1.0f + expf(-v)); }

// ---- warp-level tensor core primitives (baseline PTX, no sm_103a gating) ----
__device__ __forceinline__ void ldm_x4(uint32_t* r, uint32_t addr) {
    asm volatile("ldmatrix.sync.aligned.m8n8.x4.shared.b16 {%0,%1,%2,%3}, [%4];"
                 : "=r"(r[0]), "=r"(r[1]), "=r"(r[2]), "=r"(r[3]) : "r"(addr));
}
__device__ __forceinline__ void mma_bf16(float* c, const uint32_t* a,
                                         uint32_t b0, uint32_t b1) {
    asm volatile(
        "mma.sync.aligned.m16n8k16.row.col.f32.bf16.bf16.f32 "
        "{%0,%1,%2,%3}, {%4,%5,%6,%7}, {%8,%9}, {%0,%1,%2,%3};"
        : "+f"(c[0]), "+f"(c[1]), "+f"(c[2]), "+f"(c[3])
        : "r"(a[0]), "r"(a[1]), "r"(a[2]), "r"(a[3]), "r"(b0), "r"(b1));
}

// ---------------------------------------------------------------------------
// Convert kernels: fp32 -> bf16 hi/lo planes
// ---------------------------------------------------------------------------
__global__ void __launch_bounds__(256)
convert_x_kernel(const float* __restrict__ x) {
    int idx = blockIdx.x * 256 + threadIdx.x;     // over 8388608 float4s
    int m  = idx >> 6;
    int k4 = (idx & 63) * 4;
    int t = m >> 8;
    int b = m & 255;
    float4 v = *reinterpret_cast<const float4*>(
        &x[(size_t)b * (SEQ * 256) + t * 256 + k4]);
    float vv[4] = {v.x, v.y, v.z, v.w};
    __nv_bfloat16 hi[4], lo[4];
#pragma unroll
    for (int i = 0; i < 4; i++) {
        hi[i] = __float2bfloat16(vv[i]);
        lo[i] = __float2bfloat16(vv[i] - __bfloat162float(hi[i]));
    }
    *reinterpret_cast<uint2*>(&g_xhi[(size_t)m * 256 + k4]) =
        *reinterpret_cast<const uint2*>(hi);
    *reinterpret_cast<uint2*>(&g_xlo[(size_t)m * 256 + k4]) =
        *reinterpret_cast<const uint2*>(lo);
}

__global__ void __launch_bounds__(256)
convert_w_kernel(const float* __restrict__ Wr,
                 const float* __restrict__ Wz,
                 const float* __restrict__ Wh) {
    int idx = blockIdx.x * 256 + threadIdx.x;     // over 768*256
    int n = idx >> 8;
    int k = idx & 255;
    int g = n >> 8;
    int j = n & 255;
    const float* W = (g == 0) ? Wr : (g == 1) ? Wz : Wh;
    float v = W[k * 256 + j];
    __nv_bfloat16 hi = __float2bfloat16(v);
    __nv_bfloat16 lo = __float2bfloat16(v - __bfloat162float(hi));
    g_Whi[idx] = hi;
    g_Wlo[idx] = lo;
}

// ---------------------------------------------------------------------------
// Tensor-core precompute GEMM via mma.sync (bf16 3-term split, fp32 accum):
//   g_A[m][n] = sum_k x[m][k] * W[k][n] + bias[n]
// CTA tile 128(m) x 128(n), K chunked 8x32. 8 warps = 4(m) x 2(n);
// warp tile 32x64. A smem [128][32] (pad row->40), B smem [128][32] (pad 40).
// grid (1024, 6), 256 threads.
// ---------------------------------------------------------------------------
#define GEMM_PAD 40   // row pitch in bf16 elems (80 bytes) - conflict-free ldmatrix

__global__ void __launch_bounds__(256)
gemm_mma_kernel(const float* __restrict__ br,
                const float* __restrict__ bz,
                const float* __restrict__ bh) {
    __shared__ __nv_bfloat16 Ahi_s[128 * GEMM_PAD];
    __shared__ __nv_bfloat16 Alo_s[128 * GEMM_PAD];
    __shared__ __nv_bfloat16 Bhi_s[128 * GEMM_PAD];
    __shared__ __nv_bfloat16 Blo_s[128 * GEMM_PAD];

    const int tid = threadIdx.x;
    const int wid = tid >> 5;
    const int l   = tid & 31;
    const int wm  = wid & 3;          // m-warp 0..3
    const int wn  = wid >> 2;         // n-warp 0..1
    const int m0  = blockIdx.x * 128;
    const int n0  = blockIdx.y * 128;

    const uint32_t a_base[2] = {smem_u32(Ahi_s), smem_u32(Alo_s)};
    const uint32_t b_base[2] = {smem_u32(Bhi_s), smem_u32(Blo_s)};

    // per-lane ldmatrix offsets (bytes)
    const uint32_t aoff = (uint32_t)((l & 15) * 80 + (l >> 4) * 16);
    const uint32_t boff = (uint32_t)(((l & 7) + 8 * (l >> 4)) * 80 + ((l >> 3) & 1) * 16);

    float acc[2][8][4];
#pragma unroll
    for (int mt = 0; mt < 2; mt++)
#pragma unroll
        for (int nt = 0; nt < 8; nt++)
#pragma unroll
            for (int i = 0; i < 4; i++) acc[mt][nt][i] = 0.f;

    for (int kc = 0; kc < 8; kc++) {
        // ---- load 4 tiles (128 rows x 32 bf16 each): idx -> (row, 16B seg) ----
#pragma unroll
        for (int it = 0; it < 2; it++) {
            int idx = tid + it * 256;           // 0..511
            int row = idx >> 2;
            int seg = (idx & 3) * 8;            // bf16 elems
            size_t ga = (size_t)(m0 + row) * 256 + kc * 32 + seg;
            size_t gb = (size_t)(n0 + row) * 256 + kc * 32 + seg;
            int so = row * GEMM_PAD + seg;
            *reinterpret_cast<uint4*>(&Ahi_s[so]) = *reinterpret_cast<const uint4*>(&g_xhi[ga]);
            *reinterpret_cast<uint4*>(&Alo_s[so]) = *reinterpret_cast<const uint4*>(&g_xlo[ga]);
            *reinterpret_cast<uint4*>(&Bhi_s[so]) = *reinterpret_cast<const uint4*>(&g_Whi[gb]);
            *reinterpret_cast<uint4*>(&Blo_s[so]) = *reinterpret_cast<const uint4*>(&g_Wlo[gb]);
        }
        __syncthreads();

#pragma unroll
        for (int ks2 = 0; ks2 < 2; ks2++) {
            // plane pairs: (Ahi,Bhi), (Ahi,Blo), (Alo,Bhi)
            const int pa[3] = {0, 0, 1};
            const int pb[3] = {0, 1, 0};
#pragma unroll
            for (int pl = 0; pl < 3; pl++) {
                uint32_t af[2][4];
#pragma unroll
                for (int mt = 0; mt < 2; mt++)
                    ldm_x4(af[mt], a_base[pa[pl]] +
                           (uint32_t)((wm * 32 + mt * 16) * 80 + ks2 * 32) + aoff);
                uint32_t bf[4][4];
#pragma unroll
                for (int np = 0; np < 4; np++)
                    ldm_x4(bf[np], b_base[pb[pl]] +
                           (uint32_t)((wn * 64 + np * 16) * 80 + ks2 * 32) + boff);
#pragma unroll
                for (int mt = 0; mt < 2; mt++)
#pragma unroll
                    for (int np = 0; np < 4; np++) {
                        mma_bf16(acc[mt][np * 2 + 0], af[mt], bf[np][0], bf[np][1]);
                        mma_bf16(acc[mt][np * 2 + 1], af[mt], bf[np][2], bf[np][3]);
                    }
            }
        }
        __syncthreads();
    }

    // ---- epilogue: add bias, write g_A ----
    const int gate = n0 >> 8;
    const float* bias = (gate == 0) ? br : (gate == 1) ? bz : bh;
    const int jbase = (n0 & 255) + wn * 64;
#pragma unroll
    for (int mt = 0; mt < 2; mt++) {
        int row0 = m0 + wm * 32 + mt * 16 + (l >> 2);
#pragma unroll
        for (int nt = 0; nt < 8; nt++) {
            int jc = jbase + nt * 8 + (l & 3) * 2;
            float2 bb = *reinterpret_cast<const float2*>(&bias[jc]);
            int col = n0 + wn * 64 + nt * 8 + (l & 3) * 2;
            float2 v0, v1;
            v0.x = acc[mt][nt][0] + bb.x;
            v0.y = acc[mt][nt][1] + bb.y;
            v1.x = acc[mt][nt][2] + bb.x;
            v1.y = acc[mt][nt][3] + bb.y;
            *reinterpret_cast<float2*>(&g_A[(size_t)row0 * GATE3 + col]) = v0;
            *reinterpret_cast<float2*>(&g_A[(size_t)(row0 + 8) * GATE3 + col]) = v1;
        }
    }
}

// ---------------------------------------------------------------------------
// Recurrence (UNCHANGED from best kernel): 32 clusters x 4 CTAs x 512 threads
// ---------------------------------------------------------------------------
__global__ void __launch_bounds__(512, 1)
gru_recurrence_kernel(const float* __restrict__ Wr,
                      const float* __restrict__ Wz,
                      const float* __restrict__ Wh,
                      const float* __restrict__ Wo,
                      const float* __restrict__ bo,
                      float* __restrict__ out) {
    extern __shared__ float sm[];
    float2* Urz  = (float2*)sm;           // [256][64] (k, col) -> (Ur, Uz)
    float*  Uh_s = sm + 32768;            // [256][64]
    float*  hT   = Uh_s + 16384;          // [256 cols][8 rows]
    float*  rhT  = hT + 2048;             // [256 cols][8 rows]
    float*  red  = rhT + 2048;            // [512 threads][8], swizzled

    const int tid = threadIdx.x;
    const int q   = blockIdx.x & 3;
    const int b0  = (blockIdx.x >> 2) * 8;

    const int jj = tid & 63;
    const int ks = tid >> 6;
    const int k1_0 = ks * 32;
    const int c  = tid & 63;
    const int kq = tid >> 6;
    const int k2_0 = kq * 32;
    const int ec  = tid >> 3;
    const int em  = tid & 7;
    const int egc = q * 64 + ec;

    int widx[8];
#pragma unroll
    for (int i = 0; i < 8; i++) widx[i] = tid * 8 + ((i + (tid >> 2)) & 7);
    const int rbase = ec * 8 + ((em + (ec >> 2)) & 7);

    for (int i = tid; i < 16384; i += 512) {
        int k = i >> 6, cc = i & 63;
        int gi = (256 + k) * 256 + q * 64 + cc;
        Urz[i]  = make_float2(Wr[gi], Wz[gi]);
        Uh_s[i] = Wh[gi];
    }
    for (int i = tid; i < 2048; i += 512) hT[i] = 0.f;
    __syncthreads();

    const uint32_t rh_loc = smem_u32(&rhT[egc * 8 + em]);
    const uint32_t h_loc  = smem_u32(&hT[egc * 8 + em]);
    uint32_t rh_p[3], h_p[3];
#pragma unroll
    for (int i = 0; i < 3; i++) {
        rh_p[i] = mapa_peer(rh_loc, q ^ (i + 1));
        h_p[i]  = mapa_peer(h_loc,  q ^ (i + 1));
    }

    cluster_sync_();
    cluster_arrive_();

    float h_reg = 0.f;
    const float* Ar0 = g_A + (size_t)b0 * GATE3;
    float a_r = Ar0[em * GATE3 + egc];
    float a_z = Ar0[em * GATE3 + 256 + egc];
    float a_h = Ar0[em * GATE3 + 512 + egc];

    for (int t = 0; t < SEQ; t++) {
        cluster_wait_();

        float accr[8], accz[8];
#pragma unroll
        for (int i = 0; i < 8; i++) { accr[i] = 0.f; accz[i] = 0.f; }
#pragma unroll 8
        for (int kk = 0; kk < 32; kk++) {
            int k = k1_0 + kk;
            float2 u  = Urz[k * 64 + jj];
            float4 hA = *reinterpret_cast<const float4*>(&hT[k * 8]);
            float4 hB = *reinterpret_cast<const float4*>(&hT[k * 8 + 4]);
            accr[0] += u.x * hA.x;  accz[0] += u.y * hA.x;
            accr[1] += u.x * hA.y;  accz[1] += u.y * hA.y;
            accr[2] += u.x * hA.z;  accz[2] += u.y * hA.z;
            accr[3] += u.x * hA.w;  accz[3] += u.y * hA.w;
            accr[4] += u.x * hB.x;  accz[4] += u.y * hB.x;
            accr[5] += u.x * hB.y;  accz[5] += u.y * hB.y;
            accr[6] += u.x * hB.z;  accz[6] += u.y * hB.z;
            accr[7] += u.x * hB.w;  accz[7] += u.y * hB.w;
        }

#pragma unroll
        for (int i = 0; i < 8; i++) red[widx[i]] = accr[i];
        __syncthreads();
        {
            float s = 0.f;
#pragma unroll
            for (int p = 0; p < 8; p++) s += red[p * 512 + rbase];
            float rh = sigmoidf_(a_r + s) * h_reg;
            rhT[egc * 8 + em] = rh;
            st_cluster_f32(rh_p[0], rh);
            st_cluster_f32(rh_p[1], rh);
            st_cluster_f32(rh_p[2], rh);
        }
        cluster_arrive_();
        __syncthreads();
#pragma unroll
        for (int i = 0; i < 8; i++) red[widx[i]] = accz[i];
        __syncthreads();
        float z_reg;
        {
            float s = 0.f;
#pragma unroll
            for (int p = 0; p < 8; p++) s += red[p * 512 + rbase];
            z_reg = sigmoidf_(a_z + s);
        }
        __syncthreads();
        cluster_wait_();

        float ach[8];
#pragma unroll
        for (int i = 0; i < 8; i++) ach[i] = 0.f;
#pragma unroll 8
        for (int kk = 0; kk < 32; kk++) {
            int k = k2_0 + kk;
            float  u  = Uh_s[k * 64 + c];
            float4 rA = *reinterpret_cast<const float4*>(&rhT[k * 8]);
            float4 rB = *reinterpret_cast<const float4*>(&rhT[k * 8 + 4]);
            ach[0] += u * rA.x;  ach[1] += u * rA.y;
            ach[2] += u * rA.z;  ach[3] += u * rA.w;
            ach[4] += u * rB.x;  ach[5] += u * rB.y;
            ach[6] += u * rB.z;  ach[7] += u * rB.w;
        }
#pragma unroll
        for (int i = 0; i < 8; i++) red[widx[i]] = ach[i];
        __syncthreads();
        {
            float s = 0.f;
#pragma unroll
            for (int p = 0; p < 8; p++) s += red[p * 512 + rbase];
            float hc = tanhf(a_h + s);
            float hn = z_reg * h_reg + (1.f - z_reg) * hc;
            h_reg = hn;
            hT[egc * 8 + em] = hn;
            st_cluster_f32(h_p[0], hn);
            st_cluster_f32(h_p[1], hn);
            st_cluster_f32(h_p[2], hn);
        }
        cluster_arrive_();

        {
            int t2 = (t + 1 < SEQ) ? (t + 1) : 0;
            const float* An = g_A + ((size_t)t2 * 256 + b0) * GATE3;
            a_r = An[em * GATE3 + egc];
            a_z = An[em * GATE3 + 256 + egc];
            a_h = An[em * GATE3 + 512 + egc];
        }
    }
    cluster_wait_();

    {
        float o = 0.f;
#pragma unroll 8
        for (int k = 0; k < 256; k++)
            o += hT[k * 8 + em] * Wo[k * 256 + egc];
        out[(b0 + em) * 256 + egc] = o + bo[egc];
    }
}

// ---------------------------------------------------------------------------
// Launch
// ---------------------------------------------------------------------------
extern "C" void kernel_launch(void* const* d_in, const int* in_sizes, int n_in,
                              void* d_out, int out_size) {
    const float* x  = (const float*)d_in[0];
    const float* Wr = (const float*)d_in[1];
    const float* br = (const float*)d_in[2];
    const float* Wz = (const float*)d_in[3];
    const float* bz = (const float*)d_in[4];
    const float* Wh = (const float*)d_in[5];
    const float* bh = (const float*)d_in[6];
    const float* Wo = (const float*)d_in[7];
    const float* bo = (const float*)d_in[8];
    float* out = (float*)d_out;

    convert_x_kernel<<<32768, 256>>>(x);
    convert_w_kernel<<<768, 256>>>(Wr, Wz, Wh);
    gemm_mma_kernel<<<dim3(1024, 6), 256>>>(br, bz, bh);

    cudaFuncSetAttribute(gru_recurrence_kernel,
                         cudaFuncAttributeMaxDynamicSharedMemorySize, REC_SMEM_BYTES);
    cudaLaunchConfig_t cfg = {};
    cfg.gridDim  = dim3(128, 1, 1);
    cfg.blockDim = dim3(512, 1, 1);
    cfg.dynamicSmemBytes = REC_SMEM_BYTES;
    cfg.stream = 0;
    cudaLaunchAttribute attrs[1];
    attrs[0].id = cudaLaunchAttributeClusterDimension;
    attrs[0].val.clusterDim.x = 4;
    attrs[0].val.clusterDim.y = 1;
    attrs[0].val.clusterDim.z = 1;
    cfg.attrs = attrs;
    cfg.numAttrs = 1;
    cudaLaunchKernelEx(&cfg, gru_recurrence_kernel, Wr, Wz, Wh, Wo, bo, out);
}